// round 7
// baseline (speedup 1.0000x reference)
#include <cuda_runtime.h>
#include <cuda_fp16.h>
#include <math.h>
#include <float.h>
#include <stdint.h>

#define BB 8
#define CC 512
#define LL 8192
#define HH 8
#define DD 64

// ---------------------------------------------------------------------------
// Scratch (static device globals: allocation-free per harness rules)
// ---------------------------------------------------------------------------
// fp16 intermediates [B][C][L]
static __device__ __align__(256) __half g_Q[(size_t)BB * CC * LL];
static __device__ __align__(256) __half g_K[(size_t)BB * CC * LL];
static __device__ __align__(256) __half g_V[(size_t)BB * CC * LL];
static __device__ float g_CTX[BB * HH * DD * DD];
static __device__ float2 g_KSTAT[BB * CC];          // per-(b,c): (max, 1/sum)

// transposed fp16 operands: [B][L][C], C contiguous (K-contiguous for MMA B)
static __device__ __align__(256) __half g_X_in[(size_t)BB * LL * CC];
static __device__ __align__(256) __half g_X_ctx[(size_t)BB * LL * CC];
static __device__ __align__(256) __half g_X_att[(size_t)BB * LL * CC];
// weights fp16: 0=q 1=k 2=v 3=r   ([O][C] row-major, K-contiguous)
static __device__ __align__(256) __half g_W[4][CC * CC];

// ---------------------------------------------------------------------------
__device__ __forceinline__ uint32_t smem_u32(const void* p) {
    uint32_t a;
    asm("{ .reg .u64 t; cvta.to.shared.u64 t, %1; cvt.u32.u64 %0, t; }"
        : "=r"(a) : "l"(p));
    return a;
}
__device__ __forceinline__ void ldm_x4(uint32_t* r, uint32_t addr) {
    asm volatile("ldmatrix.sync.aligned.m8n8.x4.shared.b16 {%0,%1,%2,%3}, [%4];"
                 : "=r"(r[0]), "=r"(r[1]), "=r"(r[2]), "=r"(r[3]) : "r"(addr));
}
__device__ __forceinline__ void ldm_x2(uint32_t* r, uint32_t addr) {
    asm volatile("ldmatrix.sync.aligned.m8n8.x2.shared.b16 {%0,%1}, [%2];"
                 : "=r"(r[0]), "=r"(r[1]) : "r"(addr));
}
__device__ __forceinline__ void mma_f16(float* d, const uint32_t* a, const uint32_t* b) {
    asm volatile(
        "mma.sync.aligned.m16n8k16.row.col.f32.f16.f16.f32 "
        "{%0,%1,%2,%3}, {%4,%5,%6,%7}, {%8,%9}, {%0,%1,%2,%3};"
        : "+f"(d[0]), "+f"(d[1]), "+f"(d[2]), "+f"(d[3])
        : "r"(a[0]), "r"(a[1]), "r"(a[2]), "r"(a[3]), "r"(b[0]), "r"(b[1]));
}
__device__ __forceinline__ void cp16(uint32_t dst, const void* src) {
    asm volatile("cp.async.ca.shared.global [%0], [%1], 16;"
                 :: "r"(dst), "l"(src) : "memory");
}

// ---------------------------------------------------------------------------
// Weight convert: all 4 weights, fp32 [O,C] -> fp16
// ---------------------------------------------------------------------------
__global__ void wconv_kernel(const float* __restrict__ W0, const float* __restrict__ W1,
                             const float* __restrict__ W2, const float* __restrict__ W3,
                             __half* __restrict__ Wh)
{
    const float* Ws[4] = {W0, W1, W2, W3};
    const int i = blockIdx.x * 256 + threadIdx.x;
    Wh[blockIdx.y * CC * CC + i] = __float2half(Ws[blockIdx.y][i]);
}

// ---------------------------------------------------------------------------
// Transpose + convert: X[b][c][l] fp32 -> XT[b][l][c] fp16
// ---------------------------------------------------------------------------
__global__ __launch_bounds__(256) void tconv_kernel(
    const float* __restrict__ X, __half* __restrict__ Th)
{
    __shared__ float t[32][33];
    const int l0 = blockIdx.x * 32, c0 = blockIdx.y * 32, b = blockIdx.z;
    const float* xp = X + ((size_t)b * CC + c0) * LL + l0;
#pragma unroll
    for (int i = 0; i < 4; i++) {
        const int c = threadIdx.y + i * 8;
        t[c][threadIdx.x] = xp[(size_t)c * LL + threadIdx.x];
    }
    __syncthreads();
    __half* th = Th + ((size_t)b * LL + l0) * CC + c0;
#pragma unroll
    for (int i = 0; i < 4; i++) {
        const int row = threadIdx.y + i * 8;
        th[(size_t)row * CC + threadIdx.x] = __float2half(t[threadIdx.x][row]);
    }
}

// ---------------------------------------------------------------------------
// mma.sync fp16 GEMM, cp.async 3-stage pipeline, templated output type.
// ---------------------------------------------------------------------------
#define PADK 40
#define NCHUNK (CC / 32)
#define OFF_B 10240
#define STAGE_B 20480
#define GEMM_DSM (3 * STAGE_B)

template <typename OutT>
__global__ void __launch_bounds__(256, 2) gemm_mma_kernel(
    const __half* __restrict__ A, const __half* __restrict__ B,
    const float* __restrict__ bias, const float* __restrict__ resid,
    OutT* __restrict__ Y)
{
    extern __shared__ char dsm[];
    const uint32_t sbase = smem_u32(dsm);

    const int tid = threadIdx.x, lane = tid & 31, wid = tid >> 5;
    const int wm = wid >> 2, wn = wid & 3;
    const int b = blockIdx.z;
    const int n0 = blockIdx.x * 128;
    const int m0 = blockIdx.y * 128;

    const __half* Ar = A + (size_t)m0 * CC;
    const __half* Br = B + ((size_t)b * LL + n0) * CC;

    const int ldRow = tid >> 2;
    const int ldGrp = tid & 3;

    auto issue = [&](int kc) {
        const uint32_t sb = sbase + (uint32_t)(kc % 3) * STAGE_B;
        const size_t gc = (size_t)kc * 32 + ldGrp * 8;
#pragma unroll
        for (int p = 0; p < 2; p++) {
            const int row = ldRow + p * 64;
            const uint32_t so = sb + (uint32_t)(row * 80 + ldGrp * 16);
            const size_t go = (size_t)row * CC + gc;
            cp16(so, Ar + go);
            cp16(so + OFF_B, Br + go);
        }
        asm volatile("cp.async.commit_group;" ::: "memory");
    };

    float acc[4][4][4];
#pragma unroll
    for (int i = 0; i < 4; i++)
#pragma unroll
        for (int j = 0; j < 4; j++)
#pragma unroll
            for (int x = 0; x < 4; x++) acc[i][j][x] = 0.f;

    const uint32_t aRow = (uint32_t)(wm * 64) + (lane & 7) + (lane & 8);
    const uint32_t aKh = (lane & 16) >> 1;
    const uint32_t aOffB = (aRow * PADK + aKh) * 2;
    const uint32_t bRow = (uint32_t)(wn * 32) + (lane & 7);
    const uint32_t bKh = (uint32_t)(lane & 8);
    const uint32_t bOffB = (bRow * PADK + bKh) * 2;

    issue(0);
    issue(1);

    for (int kc = 0; kc < NCHUNK; kc++) {
        if (kc + 1 < NCHUNK) {
            asm volatile("cp.async.wait_group 1;" ::: "memory");
        } else {
            asm volatile("cp.async.wait_group 0;" ::: "memory");
        }
        __syncthreads();
        if (kc + 2 < NCHUNK) issue(kc + 2);

        const uint32_t stb = sbase + (uint32_t)(kc % 3) * STAGE_B;
#pragma unroll
        for (int ks = 0; ks < 2; ks++) {
            const uint32_t kb = ks * 32;
            uint32_t fb[4][2];
#pragma unroll
            for (int nt = 0; nt < 4; nt++)
                ldm_x2(fb[nt], stb + OFF_B + bOffB + nt * (8 * PADK * 2) + kb);
#pragma unroll
            for (int mt = 0; mt < 4; mt++) {
                uint32_t fa[4];
                ldm_x4(fa, stb + aOffB + mt * (16 * PADK * 2) + kb);
#pragma unroll
                for (int nt = 0; nt < 4; nt++)
                    mma_f16(acc[mt][nt], fa, fb[nt]);
            }
        }
    }

    const int mbase = m0 + wm * 64 + (lane >> 2);
    const int nbase = n0 + wn * 32 + (lane & 3) * 2;
#pragma unroll
    for (int mt = 0; mt < 4; mt++) {
        const int m = mbase + mt * 16;
        const float bv0 = bias[m], bv1 = bias[m + 8];
        OutT* y0 = Y + ((size_t)b * CC + m) * LL + n0;
        OutT* y1 = y0 + (size_t)8 * LL;
#pragma unroll
        for (int nt = 0; nt < 4; nt++) {
            const int n = (nbase - n0) + nt * 8;
            float v00 = acc[mt][nt][0] + bv0;
            float v01 = acc[mt][nt][1] + bv0;
            float v10 = acc[mt][nt][2] + bv1;
            float v11 = acc[mt][nt][3] + bv1;
            if constexpr (sizeof(OutT) == 4) {
                if (resid) {
                    const float* r0 = resid + ((size_t)b * CC + m) * LL + n0;
                    const float2 q0 = *(const float2*)(r0 + n);
                    const float2 q1 = *(const float2*)(r0 + (size_t)8 * LL + n);
                    v00 += q0.x; v01 += q0.y; v10 += q1.x; v11 += q1.y;
                }
                *(float2*)(y0 + n) = make_float2(v00, v01);
                *(float2*)(y1 + n) = make_float2(v10, v11);
            } else {
                *(__half2*)(y0 + n) = __floats2half2_rn(v00, v01);
                *(__half2*)(y1 + n) = __floats2half2_rn(v10, v11);
            }
        }
    }
}

// ---------------------------------------------------------------------------
// kstats: per-(b,c) row of fp16 K, compute (max, 1/sum_exp). 1 block/row.
// ---------------------------------------------------------------------------
__global__ __launch_bounds__(256) void kstats_kernel(
    const __half* __restrict__ Kh, float2* __restrict__ ST)
{
    const __half* p = Kh + (size_t)blockIdx.x * LL;
    const int tid = threadIdx.x;
    float v[32];
    float m = -FLT_MAX;
#pragma unroll
    for (int k = 0; k < 4; k++) {
        const uint4 raw = *(const uint4*)(p + ((size_t)tid + k * 256) * 8);
        const __half2* h = (const __half2*)&raw;
#pragma unroll
        for (int j = 0; j < 4; j++) {
            const float2 f = __half22float2(h[j]);
            v[k * 8 + j * 2 + 0] = f.x;
            v[k * 8 + j * 2 + 1] = f.y;
            m = fmaxf(m, fmaxf(f.x, f.y));
        }
    }
    __shared__ float red[256];
    red[tid] = m; __syncthreads();
    for (int s = 128; s > 0; s >>= 1) {
        if (tid < s) red[tid] = fmaxf(red[tid], red[tid + s]);
        __syncthreads();
    }
    m = red[0];
    __syncthreads();
    float sum = 0.f;
#pragma unroll
    for (int i = 0; i < 32; i++) sum += __expf(v[i] - m);
    red[tid] = sum; __syncthreads();
    for (int s = 128; s > 0; s >>= 1) {
        if (tid < s) red[tid] += red[tid + s];
        __syncthreads();
    }
    if (tid == 0) ST[blockIdx.x] = make_float2(m, 1.f / red[0]);
}

__global__ void zero_ctx_kernel(float* __restrict__ C)
{
    C[blockIdx.x * 256 + threadIdx.x] = 0.f;
}

// ---------------------------------------------------------------------------
// ctx[b,h,dk,dv] = sum_l softmaxK[b,h*64+dk,l] * V[b,h*64+dv,l]
// K softmax applied on the fly from precomputed stats. fp16 inputs.
// ---------------------------------------------------------------------------
__global__ __launch_bounds__(128) void ctx_kernel(
    const __half* __restrict__ Kk, const __half* __restrict__ Vv,
    const float2* __restrict__ ST, float* __restrict__ CTX)
{
    const int b = blockIdx.z, h = blockIdx.y;
    const int lStart = blockIdx.x * (LL / 16);
    const __half* kp = Kk + ((size_t)b * CC + h * DD) * LL;
    const __half* vp = Vv + ((size_t)b * CC + h * DD) * LL;

    __shared__ float ks[32][65];
    __shared__ float vs[32][65];

    const int dk0 = (threadIdx.x >> 4) * 8;
    const int dv0 = (threadIdx.x & 15) * 4;

    // per-thread staging rows are fixed across the t loop: cache their stats
    float2 st[4];
#pragma unroll
    for (int i = 0; i < 4; i++) {
        const int row = (threadIdx.x + i * 128) >> 3;
        st[i] = ST[b * CC + h * DD + row];
    }

    float acc[8][4];
#pragma unroll
    for (int i = 0; i < 8; i++)
#pragma unroll
        for (int j = 0; j < 4; j++) acc[i][j] = 0.f;

    for (int t = 0; t < LL / 16; t += 32) {
#pragma unroll
        for (int i = 0; i < 4; i++) {
            const int idx = threadIdx.x + i * 128;
            const int row = idx >> 3;
            const int col = (idx & 7) * 4;
            const size_t go = (size_t)row * LL + lStart + t + col;
            const uint2 kraw = *(const uint2*)(kp + go);
            const float2 k01 = __half22float2(*(const __half2*)&kraw.x);
            const float2 k23 = __half22float2(*(const __half2*)&kraw.y);
            ks[col + 0][row] = __expf(k01.x - st[i].x) * st[i].y;
            ks[col + 1][row] = __expf(k01.y - st[i].x) * st[i].y;
            ks[col + 2][row] = __expf(k23.x - st[i].x) * st[i].y;
            ks[col + 3][row] = __expf(k23.y - st[i].x) * st[i].y;
            const uint2 vraw = *(const uint2*)(vp + go);
            const float2 v01 = __half22float2(*(const __half2*)&vraw.x);
            const float2 v23 = __half22float2(*(const __half2*)&vraw.y);
            vs[col + 0][row] = v01.x; vs[col + 1][row] = v01.y;
            vs[col + 2][row] = v23.x; vs[col + 3][row] = v23.y;
        }
        __syncthreads();
#pragma unroll 8
        for (int ll = 0; ll < 32; ll++) {
            float a[8], bq[4];
#pragma unroll
            for (int i = 0; i < 8; i++) a[i] = ks[ll][dk0 + i];
#pragma unroll
            for (int j = 0; j < 4; j++) bq[j] = vs[ll][dv0 + j];
#pragma unroll
            for (int i = 0; i < 8; i++)
#pragma unroll
                for (int j = 0; j < 4; j++)
                    acc[i][j] = fmaf(a[i], bq[j], acc[i][j]);
        }
        __syncthreads();
    }

    float* cp = CTX + (size_t)(b * HH + h) * DD * DD;
#pragma unroll
    for (int i = 0; i < 8; i++)
#pragma unroll
        for (int j = 0; j < 4; j++)
            atomicAdd(&cp[(dk0 + i) * DD + dv0 + j], acc[i][j]);
}

// ---------------------------------------------------------------------------
// Fused att + softmax over dk, fp16 Q input, fp16 XT-layout output.
// ---------------------------------------------------------------------------
__global__ __launch_bounds__(128) void att_kernel(
    const __half* __restrict__ Q, const float* __restrict__ CTX,
    __half* __restrict__ Th)
{
    const int b = blockIdx.z, h = blockIdx.y;
    const int lBase = blockIdx.x * 128;

    __shared__ float cs[DD][DD];
    __shared__ float stage[64][65];
    const float* cp = CTX + (size_t)(b * HH + h) * DD * DD;
    for (int i = threadIdx.x; i < DD * DD; i += 128)
        ((float*)cs)[i] = cp[i];
    __syncthreads();

    const int lane5 = threadIdx.x & 31;
    const int dv0 = (threadIdx.x >> 5) * 16;
    const int l0 = lBase + lane5 * 4;
    const __half* qp = Q + ((size_t)b * CC + h * DD) * LL;

    float mx[4] = {-FLT_MAX, -FLT_MAX, -FLT_MAX, -FLT_MAX};
#pragma unroll 8
    for (int dk = 0; dk < DD; dk++) {
        const uint2 raw = *(const uint2*)(qp + (size_t)dk * LL + l0);
        const float2 q01 = __half22float2(*(const __half2*)&raw.x);
        const float2 q23 = __half22float2(*(const __half2*)&raw.y);
        mx[0] = fmaxf(mx[0], q01.x);
        mx[1] = fmaxf(mx[1], q01.y);
        mx[2] = fmaxf(mx[2], q23.x);
        mx[3] = fmaxf(mx[3], q23.y);
    }

    float acc[16][4];
#pragma unroll
    for (int j = 0; j < 16; j++)
#pragma unroll
        for (int i = 0; i < 4; i++) acc[j][i] = 0.f;
    float sum[4] = {0.f, 0.f, 0.f, 0.f};

#pragma unroll 4
    for (int dk = 0; dk < DD; dk++) {
        const uint2 raw = *(const uint2*)(qp + (size_t)dk * LL + l0);
        const float2 q01 = __half22float2(*(const __half2*)&raw.x);
        const float2 q23 = __half22float2(*(const __half2*)&raw.y);
        float e0 = __expf(q01.x - mx[0]);
        float e1 = __expf(q01.y - mx[1]);
        float e2 = __expf(q23.x - mx[2]);
        float e3 = __expf(q23.y - mx[3]);
        sum[0] += e0; sum[1] += e1; sum[2] += e2; sum[3] += e3;
#pragma unroll
        for (int j = 0; j < 16; j++) {
            const float c = cs[dk][dv0 + j];
            acc[j][0] = fmaf(c, e0, acc[j][0]);
            acc[j][1] = fmaf(c, e1, acc[j][1]);
            acc[j][2] = fmaf(c, e2, acc[j][2]);
            acc[j][3] = fmaf(c, e3, acc[j][3]);
        }
    }
    const float inv0 = 1.f / sum[0], inv1 = 1.f / sum[1];
    const float inv2 = 1.f / sum[2], inv3 = 1.f / sum[3];
#pragma unroll
    for (int j = 0; j < 16; j++) {
        acc[j][0] *= inv0; acc[j][1] *= inv1;
        acc[j][2] *= inv2; acc[j][3] *= inv3;
    }

#pragma unroll
    for (int half_i = 0; half_i < 2; half_i++) {
        __syncthreads();
        if ((lane5 >> 4) == half_i) {
            const int lr = (lane5 & 15) * 4;
#pragma unroll
            for (int i = 0; i < 4; i++)
#pragma unroll
                for (int j = 0; j < 16; j++)
                    stage[lr + i][dv0 + j] = acc[j][i];
        }
        __syncthreads();
        const int r0 = threadIdx.x >> 2;
        const int sub = threadIdx.x & 3;
#pragma unroll
        for (int rr = 0; rr < 2; rr++) {
            const int r = r0 + rr * 32;
            __half hh[16];
#pragma unroll
            for (int k = 0; k < 16; k++)
                hh[k] = __float2half(stage[r][sub * 16 + k]);
            const size_t o = ((size_t)b * LL + lBase + half_i * 64 + r) * CC
                             + h * DD + sub * 16;
            *(uint4*)(Th + o) = *(const uint4*)hh;
            *(uint4*)(Th + o + 8) = *(const uint4*)(hh + 8);
        }
    }
}

// ---------------------------------------------------------------------------
extern "C" void kernel_launch(void* const* d_in, const int* in_sizes, int n_in,
                              void* d_out, int out_size)
{
    const float* input_ = (const float*)d_in[0];
    const float* context_ = (const float*)d_in[1];
    const float* Wk = (const float*)d_in[2];
    const float* bk = (const float*)d_in[3];
    const float* Wq = (const float*)d_in[4];
    const float* bq = (const float*)d_in[5];
    const float* Wv = (const float*)d_in[6];
    const float* bv = (const float*)d_in[7];
    const float* Wr = (const float*)d_in[8];
    const float* br = (const float*)d_in[9];
    float* out = (float*)d_out;

    __half *Qp, *Kp, *Vp;
    float* Cp;
    float2* STp;
    cudaGetSymbolAddress((void**)&Qp, g_Q);
    cudaGetSymbolAddress((void**)&Kp, g_K);
    cudaGetSymbolAddress((void**)&Vp, g_V);
    cudaGetSymbolAddress((void**)&Cp, g_CTX);
    cudaGetSymbolAddress((void**)&STp, g_KSTAT);

    __half *Xin, *Xctx, *Xatt, *Wp;
    cudaGetSymbolAddress((void**)&Xin, g_X_in);
    cudaGetSymbolAddress((void**)&Xctx, g_X_ctx);
    cudaGetSymbolAddress((void**)&Xatt, g_X_att);
    cudaGetSymbolAddress((void**)&Wp, g_W);

    static bool attr_set = false;
    if (!attr_set) {
        cudaFuncSetAttribute(gemm_mma_kernel<__half>,
                             cudaFuncAttributeMaxDynamicSharedMemorySize, GEMM_DSM);
        cudaFuncSetAttribute(gemm_mma_kernel<float>,
                             cudaFuncAttributeMaxDynamicSharedMemorySize, GEMM_DSM);
        attr_set = true;
    }

    // weight conversions (0=q 1=k 2=v 3=r) in one launch
    wconv_kernel<<<dim3(CC * CC / 256, 4), 256>>>(Wq, Wk, Wv, Wr, Wp);

    // input transposes + fp16 convert
    const dim3 gT(LL / 32, CC / 32, BB);
    tconv_kernel<<<gT, dim3(32, 8)>>>(input_, Xin);
    tconv_kernel<<<gT, dim3(32, 8)>>>(context_, Xctx);

    // projections (fp16 in, fp16 out)
    const dim3 gG(LL / 128, CC / 128, BB);
    gemm_mma_kernel<__half><<<gG, 256, GEMM_DSM>>>(Wp + 0 * CC * CC, Xin, bq, nullptr, Qp);
    gemm_mma_kernel<__half><<<gG, 256, GEMM_DSM>>>(Wp + 1 * CC * CC, Xctx, bk, nullptr, Kp);
    gemm_mma_kernel<__half><<<gG, 256, GEMM_DSM>>>(Wp + 2 * CC * CC, Xctx, bv, nullptr, Vp);

    // attention middle: K softmax folded into ctx via row stats
    kstats_kernel<<<BB * CC, 256>>>(Kp, STp);
    zero_ctx_kernel<<<(BB * HH * DD * DD) / 256, 256>>>(Cp);
    ctx_kernel<<<dim3(16, HH, BB), 128>>>(Kp, Vp, STp, Cp);
    att_kernel<<<dim3(LL / 128, HH, BB), 128>>>(Qp, Cp, Xatt);

    // output projection (+ residual), fp32 out
    gemm_mma_kernel<float><<<gG, 256, GEMM_DSM>>>(Wp + 3 * CC * CC, Xatt, br, input_, out);
}

// round 8
// speedup vs baseline: 1.3201x; 1.3201x over previous
#include <cuda_runtime.h>
#include <cuda_fp16.h>
#include <math.h>
#include <float.h>
#include <stdint.h>

#define BB 8
#define CC 512
#define LL 8192
#define HH 8
#define DD 64

// ---------------------------------------------------------------------------
// Scratch (static device globals: allocation-free per harness rules)
// ---------------------------------------------------------------------------
static __device__ __align__(256) __half g_Q[(size_t)BB * CC * LL];
static __device__ __align__(256) __half g_K[(size_t)BB * CC * LL];
static __device__ __align__(256) __half g_V[(size_t)BB * CC * LL];
static __device__ float g_CTX[BB * HH * DD * DD];
static __device__ float2 g_KSTAT[BB * CC];                 // per-(b,c): (max, 1/sum)
static __device__ float2 g_QSTAT[(size_t)BB * HH * LL];    // per-(b,h,l): (max, 1/sum)

static __device__ __align__(256) __half g_X_in[(size_t)BB * LL * CC];
static __device__ __align__(256) __half g_X_ctx[(size_t)BB * LL * CC];
static __device__ __align__(256) __half g_X_att[(size_t)BB * LL * CC];
static __device__ __align__(256) __half g_W[4][CC * CC];

// ---------------------------------------------------------------------------
__device__ __forceinline__ uint32_t smem_u32(const void* p) {
    uint32_t a;
    asm("{ .reg .u64 t; cvta.to.shared.u64 t, %1; cvt.u32.u64 %0, t; }"
        : "=r"(a) : "l"(p));
    return a;
}
__device__ __forceinline__ void ldm_x4(uint32_t* r, uint32_t addr) {
    asm volatile("ldmatrix.sync.aligned.m8n8.x4.shared.b16 {%0,%1,%2,%3}, [%4];"
                 : "=r"(r[0]), "=r"(r[1]), "=r"(r[2]), "=r"(r[3]) : "r"(addr));
}
__device__ __forceinline__ void ldm_x4t(uint32_t* r, uint32_t addr) {
    asm volatile("ldmatrix.sync.aligned.m8n8.x4.trans.shared.b16 {%0,%1,%2,%3}, [%4];"
                 : "=r"(r[0]), "=r"(r[1]), "=r"(r[2]), "=r"(r[3]) : "r"(addr));
}
__device__ __forceinline__ void mma_f16(float* d, const uint32_t* a, const uint32_t* b) {
    asm volatile(
        "mma.sync.aligned.m16n8k16.row.col.f32.f16.f16.f32 "
        "{%0,%1,%2,%3}, {%4,%5,%6,%7}, {%8,%9}, {%0,%1,%2,%3};"
        : "+f"(d[0]), "+f"(d[1]), "+f"(d[2]), "+f"(d[3])
        : "r"(a[0]), "r"(a[1]), "r"(a[2]), "r"(a[3]), "r"(b[0]), "r"(b[1]));
}
__device__ __forceinline__ void cp16(uint32_t dst, const void* src) {
    asm volatile("cp.async.ca.shared.global [%0], [%1], 16;"
                 :: "r"(dst), "l"(src) : "memory");
}

// ---------------------------------------------------------------------------
// Weight convert: all 4 weights, fp32 [O,C] -> fp16
// ---------------------------------------------------------------------------
__global__ void wconv_kernel(const float* __restrict__ W0, const float* __restrict__ W1,
                             const float* __restrict__ W2, const float* __restrict__ W3,
                             __half* __restrict__ Wh)
{
    const float* Ws[4] = {W0, W1, W2, W3};
    const int i = blockIdx.x * 256 + threadIdx.x;
    Wh[blockIdx.y * CC * CC + i] = __float2half(Ws[blockIdx.y][i]);
}

// ---------------------------------------------------------------------------
// Transpose + convert: X[b][c][l] fp32 -> XT[b][l][c] fp16
// ---------------------------------------------------------------------------
__global__ __launch_bounds__(256) void tconv_kernel(
    const float* __restrict__ X, __half* __restrict__ Th)
{
    __shared__ float t[32][33];
    const int l0 = blockIdx.x * 32, c0 = blockIdx.y * 32, b = blockIdx.z;
    const float* xp = X + ((size_t)b * CC + c0) * LL + l0;
#pragma unroll
    for (int i = 0; i < 4; i++) {
        const int c = threadIdx.y + i * 8;
        t[c][threadIdx.x] = xp[(size_t)c * LL + threadIdx.x];
    }
    __syncthreads();
    __half* th = Th + ((size_t)b * LL + l0) * CC + c0;
#pragma unroll
    for (int i = 0; i < 4; i++) {
        const int row = threadIdx.y + i * 8;
        th[(size_t)row * CC + threadIdx.x] = __float2half(t[threadIdx.x][row]);
    }
}

// ---------------------------------------------------------------------------
// mma.sync fp16 GEMM, cp.async 3-stage pipeline, templated output type.
// B fragments loaded as paired ldmatrix.x4 (2 n-tiles per LDSM).
// ---------------------------------------------------------------------------
#define PADK 40
#define NCHUNK (CC / 32)
#define OFF_B 10240
#define STAGE_B 20480
#define GEMM_DSM (3 * STAGE_B)

template <typename OutT>
__global__ void __launch_bounds__(256, 2) gemm_mma_kernel(
    const __half* __restrict__ A, const __half* __restrict__ B,
    const float* __restrict__ bias, const float* __restrict__ resid,
    OutT* __restrict__ Y)
{
    extern __shared__ char dsm[];
    const uint32_t sbase = smem_u32(dsm);

    const int tid = threadIdx.x, lane = tid & 31, wid = tid >> 5;
    const int wm = wid >> 2, wn = wid & 3;
    const int b = blockIdx.z;
    const int n0 = blockIdx.x * 128;
    const int m0 = blockIdx.y * 128;

    const __half* Ar = A + (size_t)m0 * CC;
    const __half* Br = B + ((size_t)b * LL + n0) * CC;

    const int ldRow = tid >> 2;
    const int ldGrp = tid & 3;

    auto issue = [&](int kc) {
        const uint32_t sb = sbase + (uint32_t)(kc % 3) * STAGE_B;
        const size_t gc = (size_t)kc * 32 + ldGrp * 8;
#pragma unroll
        for (int p = 0; p < 2; p++) {
            const int row = ldRow + p * 64;
            const uint32_t so = sb + (uint32_t)(row * 80 + ldGrp * 16);
            const size_t go = (size_t)row * CC + gc;
            cp16(so, Ar + go);
            cp16(so + OFF_B, Br + go);
        }
        asm volatile("cp.async.commit_group;" ::: "memory");
    };

    float acc[4][4][4];
#pragma unroll
    for (int i = 0; i < 4; i++)
#pragma unroll
        for (int j = 0; j < 4; j++)
#pragma unroll
            for (int x = 0; x < 4; x++) acc[i][j][x] = 0.f;

    const uint32_t aRow = (uint32_t)(wm * 64) + (lane & 7) + (lane & 8);
    const uint32_t aKh = (lane & 16) >> 1;
    const uint32_t aOffB = (aRow * PADK + aKh) * 2;
    // paired B: lanes 0-7 (ntA,k0), 8-15 (ntA,k8), 16-23 (ntB,k0), 24-31 (ntB,k8)
    const uint32_t bRow2 = (uint32_t)(wn * 32) + ((lane & 16) >> 1) + (lane & 7);
    const uint32_t bOff2 = (bRow2 * PADK + (lane & 8)) * 2;

    issue(0);
    issue(1);

    for (int kc = 0; kc < NCHUNK; kc++) {
        if (kc + 1 < NCHUNK) {
            asm volatile("cp.async.wait_group 1;" ::: "memory");
        } else {
            asm volatile("cp.async.wait_group 0;" ::: "memory");
        }
        __syncthreads();
        if (kc + 2 < NCHUNK) issue(kc + 2);

        const uint32_t stb = sbase + (uint32_t)(kc % 3) * STAGE_B;
#pragma unroll
        for (int ks = 0; ks < 2; ks++) {
            const uint32_t kb = ks * 32;
            uint32_t fb[4][2];
#pragma unroll
            for (int p = 0; p < 2; p++) {
                uint32_t t4[4];
                ldm_x4(t4, stb + OFF_B + bOff2 + p * (16 * PADK * 2) + kb);
                fb[2 * p][0] = t4[0]; fb[2 * p][1] = t4[1];
                fb[2 * p + 1][0] = t4[2]; fb[2 * p + 1][1] = t4[3];
            }
#pragma unroll
            for (int mt = 0; mt < 4; mt++) {
                uint32_t fa[4];
                ldm_x4(fa, stb + aOffB + mt * (16 * PADK * 2) + kb);
#pragma unroll
                for (int nt = 0; nt < 4; nt++)
                    mma_f16(acc[mt][nt], fa, fb[nt]);
            }
        }
    }

    const int mbase = m0 + wm * 64 + (lane >> 2);
    const int nbase = n0 + wn * 32 + (lane & 3) * 2;
#pragma unroll
    for (int mt = 0; mt < 4; mt++) {
        const int m = mbase + mt * 16;
        const float bv0 = bias[m], bv1 = bias[m + 8];
        OutT* y0 = Y + ((size_t)b * CC + m) * LL + n0;
        OutT* y1 = y0 + (size_t)8 * LL;
#pragma unroll
        for (int nt = 0; nt < 4; nt++) {
            const int n = (nbase - n0) + nt * 8;
            float v00 = acc[mt][nt][0] + bv0;
            float v01 = acc[mt][nt][1] + bv0;
            float v10 = acc[mt][nt][2] + bv1;
            float v11 = acc[mt][nt][3] + bv1;
            if constexpr (sizeof(OutT) == 4) {
                if (resid) {
                    const float* r0 = resid + ((size_t)b * CC + m) * LL + n0;
                    const float2 q0 = *(const float2*)(r0 + n);
                    const float2 q1 = *(const float2*)(r0 + (size_t)8 * LL + n);
                    v00 += q0.x; v01 += q0.y; v10 += q1.x; v11 += q1.y;
                }
                *(float2*)(y0 + n) = make_float2(v00, v01);
                *(float2*)(y1 + n) = make_float2(v10, v11);
            } else {
                *(__half2*)(y0 + n) = __floats2half2_rn(v00, v01);
                *(__half2*)(y1 + n) = __floats2half2_rn(v10, v11);
            }
        }
    }
}

// ---------------------------------------------------------------------------
// kstats: per-(b,c) row of fp16 K over L: (max, 1/sum_exp). 1 block/row.
// ---------------------------------------------------------------------------
__global__ __launch_bounds__(256) void kstats_kernel(
    const __half* __restrict__ Kh, float2* __restrict__ ST)
{
    const __half* p = Kh + (size_t)blockIdx.x * LL;
    const int tid = threadIdx.x;
    float v[32];
    float m = -FLT_MAX;
#pragma unroll
    for (int k = 0; k < 4; k++) {
        const uint4 raw = *(const uint4*)(p + ((size_t)tid + k * 256) * 8);
        const __half2* h = (const __half2*)&raw;
#pragma unroll
        for (int j = 0; j < 4; j++) {
            const float2 f = __half22float2(h[j]);
            v[k * 8 + j * 2 + 0] = f.x;
            v[k * 8 + j * 2 + 1] = f.y;
            m = fmaxf(m, fmaxf(f.x, f.y));
        }
    }
    __shared__ float red[256];
    red[tid] = m; __syncthreads();
    for (int s = 128; s > 0; s >>= 1) {
        if (tid < s) red[tid] = fmaxf(red[tid], red[tid + s]);
        __syncthreads();
    }
    m = red[0];
    __syncthreads();
    float sum = 0.f;
#pragma unroll
    for (int i = 0; i < 32; i++) sum += __expf(v[i] - m);
    red[tid] = sum; __syncthreads();
    for (int s = 128; s > 0; s >>= 1) {
        if (tid < s) red[tid] += red[tid + s];
        __syncthreads();
    }
    if (tid == 0) ST[blockIdx.x] = make_float2(m, 1.f / red[0]);
}

// ---------------------------------------------------------------------------
// qstats: per-(b,h,l), over the 64 dk channels of Q: (max, 1/sum_exp).
// grid (LL/256, HH, BB)
// ---------------------------------------------------------------------------
__global__ __launch_bounds__(256) void qstats_kernel(
    const __half* __restrict__ Qh, float2* __restrict__ ST)
{
    const int l = blockIdx.x * 256 + threadIdx.x;
    const int h = blockIdx.y, b = blockIdx.z;
    const __half* qp = Qh + ((size_t)b * CC + h * DD) * LL + l;
    float v[DD];
    float m = -FLT_MAX;
#pragma unroll
    for (int d = 0; d < DD; d++) {
        v[d] = __half2float(qp[(size_t)d * LL]);
        m = fmaxf(m, v[d]);
    }
    float s = 0.f;
#pragma unroll
    for (int d = 0; d < DD; d++) s += __expf(v[d] - m);
    ST[((size_t)b * HH + h) * LL + l] = make_float2(m, 1.f / s);
}

__global__ void zero_ctx_kernel(float* __restrict__ C)
{
    C[blockIdx.x * 256 + threadIdx.x] = 0.f;
}

// ---------------------------------------------------------------------------
// ctx (tensor core): ctx[dk,dv] += inv[dk] * sum_l exp(K[dk,l]-m[dk]) * V[dv,l]
// grid (16, HH, BB), 128 threads (4 warps, 2x2), l-span 512 per block.
// ---------------------------------------------------------------------------
#define PADL 72

__global__ __launch_bounds__(128, 4) void ctx_tc_kernel(
    const __half* __restrict__ Kk, const __half* __restrict__ Vv,
    const float2* __restrict__ ST, float* __restrict__ CTX)
{
    __shared__ __half sP[64 * PADL];
    __shared__ __half sV[64 * PADL];
    const int b = blockIdx.z, h = blockIdx.y;
    const int tid = threadIdx.x, lane = tid & 31, wid = tid >> 5;
    const int wm = wid >> 1, wn = wid & 1;
    const __half* kp = Kk + ((size_t)b * CC + h * DD) * LL;
    const __half* vp = Vv + ((size_t)b * CC + h * DD) * LL;
    const float2* stp = ST + b * CC + h * DD;

    float acc[2][4][4];
#pragma unroll
    for (int i = 0; i < 2; i++)
#pragma unroll
        for (int j = 0; j < 4; j++)
#pragma unroll
            for (int x = 0; x < 4; x++) acc[i][j][x] = 0.f;

    const uint32_t sPb = smem_u32(sP), sVb = smem_u32(sV);
    const uint32_t aOff =
        (((uint32_t)(wm * 32) + (lane & 7) + (lane & 8)) * PADL + ((lane & 16) >> 1)) * 2;
    const uint32_t bOff =
        (((uint32_t)(wn * 32) + ((lane & 16) >> 1) + (lane & 7)) * PADL + (lane & 8)) * 2;

    for (int t = 0; t < 8; t++) {
        const int lt = blockIdx.x * 512 + t * 64;
#pragma unroll
        for (int it = 0; it < 4; it++) {
            const int id = tid + it * 128;
            const int row = id >> 3, l8 = (id & 7) * 8;
            const uint4 kraw = *(const uint4*)(kp + (size_t)row * LL + lt + l8);
            const float2 st = stp[row];
            const __half2* kh = (const __half2*)&kraw;
            __half hk[8];
#pragma unroll
            for (int j = 0; j < 4; j++) {
                const float2 f = __half22float2(kh[j]);
                hk[2 * j + 0] = __float2half(__expf(f.x - st.x));
                hk[2 * j + 1] = __float2half(__expf(f.y - st.x));
            }
            *(uint4*)(sP + row * PADL + l8) = *(const uint4*)hk;
            *(uint4*)(sV + row * PADL + l8) =
                *(const uint4*)(vp + (size_t)row * LL + lt + l8);
        }
        __syncthreads();
#pragma unroll
        for (int ks = 0; ks < 4; ks++) {
            const uint32_t kb = ks * 32;
            uint32_t fb[4][2];
#pragma unroll
            for (int p = 0; p < 2; p++) {
                uint32_t t4[4];
                ldm_x4(t4, sVb + bOff + p * (16 * PADL * 2) + kb);
                fb[2 * p][0] = t4[0]; fb[2 * p][1] = t4[1];
                fb[2 * p + 1][0] = t4[2]; fb[2 * p + 1][1] = t4[3];
            }
#pragma unroll
            for (int mt = 0; mt < 2; mt++) {
                uint32_t fa[4];
                ldm_x4(fa, sPb + aOff + mt * (16 * PADL * 2) + kb);
#pragma unroll
                for (int nt = 0; nt < 4; nt++)
                    mma_f16(acc[mt][nt], fa, fb[nt]);
            }
        }
        __syncthreads();
    }

    float* cpx = CTX + (size_t)(b * HH + h) * DD * DD;
#pragma unroll
    for (int mt = 0; mt < 2; mt++) {
        const int dk0 = wm * 32 + mt * 16 + (lane >> 2);
        const float inv0 = stp[dk0].y, inv1 = stp[dk0 + 8].y;
#pragma unroll
        for (int nt = 0; nt < 4; nt++) {
            const int dv = wn * 32 + nt * 8 + (lane & 3) * 2;
            atomicAdd(&cpx[dk0 * DD + dv],           acc[mt][nt][0] * inv0);
            atomicAdd(&cpx[dk0 * DD + dv + 1],       acc[mt][nt][1] * inv0);
            atomicAdd(&cpx[(dk0 + 8) * DD + dv],     acc[mt][nt][2] * inv1);
            atomicAdd(&cpx[(dk0 + 8) * DD + dv + 1], acc[mt][nt][3] * inv1);
        }
    }
}

// ---------------------------------------------------------------------------
// att (tensor core): att[dv,l] = sum_dk ctxN[dk,dv] * exp(Q[dk,l]-qm[l])*qinv[l]
// A = ctx^T [dv][dk] (regular ldmatrix), B = P [dk][l] via ldmatrix.trans.
// Output written transposed to XT fp16 [b][l][h*64+dv] via smem stage.
// grid (LL/256, HH, BB), 256 threads (8 warps, 2m x 4n).
// ---------------------------------------------------------------------------
#define PADQ 264   // P row: 256 l + 8 pad halves
#define PADT 72    // tsT row: 64 dv + 8 pad halves

__global__ __launch_bounds__(256, 2) void att_tc_kernel(
    const __half* __restrict__ Q, const float* __restrict__ CTX,
    const float2* __restrict__ QST, __half* __restrict__ Th)
{
    __shared__ __half sA[64 * PADL];        // ctx^T [dv][dk]
    __shared__ __half sP[256 * PADT];       // P [64][PADQ] then reused as tsT[256][PADT]
    const int b = blockIdx.z, h = blockIdx.y;
    const int lBase = blockIdx.x * 256;
    const int tid = threadIdx.x, lane = tid & 31, wid = tid >> 5;
    const int wm = wid >> 2, wn = wid & 3;

    // stage ctx^T (fp32 -> fp16)
    const float* cpx = CTX + (size_t)(b * HH + h) * DD * DD;
#pragma unroll
    for (int it = 0; it < 16; it++) {
        const int id = tid + it * 256;
        const int dv = id & 63, dk = id >> 6;
        sA[dv * PADL + dk] = __float2half(cpx[dk * DD + dv]);
    }
    // stage P = softmaxQ in natural [dk][l] layout (coalesced read+write)
    const __half* qp = Q + ((size_t)b * CC + h * DD) * LL + lBase;
    const float2* qs = QST + ((size_t)b * HH + h) * LL + lBase;
#pragma unroll
    for (int it = 0; it < 8; it++) {
        const int id = tid + it * 256;
        const int dk = id >> 5, l8 = (id & 31) * 8;
        const uint4 raw = *(const uint4*)(qp + (size_t)dk * LL + l8);
        const __half2* qh = (const __half2*)&raw;
        __half hq[8];
#pragma unroll
        for (int j = 0; j < 4; j++) {
            const float2 f = __half22float2(qh[j]);
            const float2 s0 = qs[l8 + 2 * j], s1 = qs[l8 + 2 * j + 1];
            hq[2 * j + 0] = __float2half(__expf(f.x - s0.x) * s0.y);
            hq[2 * j + 1] = __float2half(__expf(f.y - s1.x) * s1.y);
        }
        *(uint4*)(sP + dk * PADQ + l8) = *(const uint4*)hq;
    }
    __syncthreads();

    float acc[2][8][4];
#pragma unroll
    for (int i = 0; i < 2; i++)
#pragma unroll
        for (int j = 0; j < 8; j++)
#pragma unroll
            for (int x = 0; x < 4; x++) acc[i][j][x] = 0.f;

    const uint32_t sAb = smem_u32(sA), sPb = smem_u32(sP);
    const uint32_t aOff =
        (((uint32_t)(wm * 32) + (lane & 7) + (lane & 8)) * PADL + ((lane & 16) >> 1)) * 2;
    // trans-B: lanes 0-15 rows k0-15 (ntA), 16-31 same rows at +8 cols (ntB)
    const uint32_t bOffT =
        (((uint32_t)(lane & 15)) * PADQ + (uint32_t)(wn * 64) + ((lane & 16) >> 1)) * 2;

#pragma unroll
    for (int ks = 0; ks < 4; ks++) {
        uint32_t fa[2][4];
#pragma unroll
        for (int mt = 0; mt < 2; mt++)
            ldm_x4(fa[mt], sAb + aOff + mt * (16 * PADL * 2) + ks * 32);
        uint32_t fb[8][2];
#pragma unroll
        for (int p = 0; p < 4; p++) {
            uint32_t t4[4];
            ldm_x4t(t4, sPb + bOffT + (uint32_t)(ks * 16 * PADQ * 2) + p * 32);
            fb[2 * p][0] = t4[0]; fb[2 * p][1] = t4[1];
            fb[2 * p + 1][0] = t4[2]; fb[2 * p + 1][1] = t4[3];
        }
#pragma unroll
        for (int mt = 0; mt < 2; mt++)
#pragma unroll
            for (int nt = 0; nt < 8; nt++)
                mma_f16(acc[mt][nt], fa[mt], fb[nt]);
    }
    __syncthreads();

    // transpose to tsT[l][dv] (reuse sP), then coalesced fp16 writes
    __half* tsT = sP;
#pragma unroll
    for (int mt = 0; mt < 2; mt++) {
        const int m = wm * 32 + mt * 16 + (lane >> 2);
#pragma unroll
        for (int nt = 0; nt < 8; nt++) {
            const int n = wn * 64 + nt * 8 + (lane & 3) * 2;
            tsT[n * PADT + m]           = __float2half(acc[mt][nt][0]);
            tsT[(n + 1) * PADT + m]     = __float2half(acc[mt][nt][1]);
            tsT[n * PADT + m + 8]       = __float2half(acc[mt][nt][2]);
            tsT[(n + 1) * PADT + m + 8] = __float2half(acc[mt][nt][3]);
        }
    }
    __syncthreads();
    __half* outp = Th + ((size_t)b * LL + lBase + tid) * CC + h * DD;
#pragma unroll
    for (int j = 0; j < 8; j++)
        *(uint4*)(outp + j * 8) = *(const uint4*)(tsT + tid * PADT + j * 8);
}

// ---------------------------------------------------------------------------
extern "C" void kernel_launch(void* const* d_in, const int* in_sizes, int n_in,
                              void* d_out, int out_size)
{
    const float* input_ = (const float*)d_in[0];
    const float* context_ = (const float*)d_in[1];
    const float* Wk = (const float*)d_in[2];
    const float* bk = (const float*)d_in[3];
    const float* Wq = (const float*)d_in[4];
    const float* bq = (const float*)d_in[5];
    const float* Wv = (const float*)d_in[6];
    const float* bv = (const float*)d_in[7];
    const float* Wr = (const float*)d_in[8];
    const float* br = (const float*)d_in[9];
    float* out = (float*)d_out;

    __half *Qp, *Kp, *Vp;
    float* Cp;
    float2 *STp, *QSTp;
    cudaGetSymbolAddress((void**)&Qp, g_Q);
    cudaGetSymbolAddress((void**)&Kp, g_K);
    cudaGetSymbolAddress((void**)&Vp, g_V);
    cudaGetSymbolAddress((void**)&Cp, g_CTX);
    cudaGetSymbolAddress((void**)&STp, g_KSTAT);
    cudaGetSymbolAddress((void**)&QSTp, g_QSTAT);

    __half *Xin, *Xctx, *Xatt, *Wp;
    cudaGetSymbolAddress((void**)&Xin, g_X_in);
    cudaGetSymbolAddress((void**)&Xctx, g_X_ctx);
    cudaGetSymbolAddress((void**)&Xatt, g_X_att);
    cudaGetSymbolAddress((void**)&Wp, g_W);

    static bool attr_set = false;
    if (!attr_set) {
        cudaFuncSetAttribute(gemm_mma_kernel<__half>,
                             cudaFuncAttributeMaxDynamicSharedMemorySize, GEMM_DSM);
        cudaFuncSetAttribute(gemm_mma_kernel<float>,
                             cudaFuncAttributeMaxDynamicSharedMemorySize, GEMM_DSM);
        attr_set = true;
    }

    wconv_kernel<<<dim3(CC * CC / 256, 4), 256>>>(Wq, Wk, Wv, Wr, Wp);

    const dim3 gT(LL / 32, CC / 32, BB);
    tconv_kernel<<<gT, dim3(32, 8)>>>(input_, Xin);
    tconv_kernel<<<gT, dim3(32, 8)>>>(context_, Xctx);

    const dim3 gG(LL / 128, CC / 128, BB);
    gemm_mma_kernel<__half><<<gG, 256, GEMM_DSM>>>(Wp + 0 * CC * CC, Xin, bq, nullptr, Qp);
    gemm_mma_kernel<__half><<<gG, 256, GEMM_DSM>>>(Wp + 1 * CC * CC, Xctx, bk, nullptr, Kp);
    gemm_mma_kernel<__half><<<gG, 256, GEMM_DSM>>>(Wp + 2 * CC * CC, Xctx, bv, nullptr, Vp);

    kstats_kernel<<<BB * CC, 256>>>(Kp, STp);
    qstats_kernel<<<dim3(LL / 256, HH, BB), 256>>>(Qp, QSTp);
    zero_ctx_kernel<<<(BB * HH * DD * DD) / 256, 256>>>(Cp);
    ctx_tc_kernel<<<dim3(16, HH, BB), 128>>>(Kp, Vp, STp, Cp);
    att_tc_kernel<<<dim3(LL / 256, HH, BB), 256>>>(Qp, Cp, QSTp, Xatt);

    gemm_mma_kernel<float><<<gG, 256, GEMM_DSM>>>(Wp + 3 * CC * CC, Xatt, br, input_, out);
}

// round 10
// speedup vs baseline: 1.3660x; 1.0348x over previous
#include <cuda_runtime.h>
#include <cuda_fp16.h>
#include <math.h>
#include <float.h>
#include <stdint.h>

#define BB 8
#define CC 512
#define LL 8192
#define HH 8
#define DD 64

// ---------------------------------------------------------------------------
// Scratch (static device globals: allocation-free per harness rules)
// ---------------------------------------------------------------------------
static __device__ __align__(256) __half g_Q[(size_t)BB * CC * LL];
static __device__ __align__(256) __half g_K[(size_t)BB * CC * LL];
static __device__ __align__(256) __half g_V[(size_t)BB * CC * LL];
static __device__ float g_CTX[BB * HH * DD * DD];
static __device__ float2 g_KSTAT[BB * CC];                 // per-(b,c): (max, 1/sum)

static __device__ __align__(256) __half g_X_in[(size_t)BB * LL * CC];
static __device__ __align__(256) __half g_X_ctx[(size_t)BB * LL * CC];
static __device__ __align__(256) __half g_X_att[(size_t)BB * LL * CC];
static __device__ __align__(256) __half g_W[4][CC * CC];

// ---------------------------------------------------------------------------
__device__ __forceinline__ uint32_t smem_u32(const void* p) {
    uint32_t a;
    asm("{ .reg .u64 t; cvta.to.shared.u64 t, %1; cvt.u32.u64 %0, t; }"
        : "=r"(a) : "l"(p));
    return a;
}
__device__ __forceinline__ void ldm_x4(uint32_t* r, uint32_t addr) {
    asm volatile("ldmatrix.sync.aligned.m8n8.x4.shared.b16 {%0,%1,%2,%3}, [%4];"
                 : "=r"(r[0]), "=r"(r[1]), "=r"(r[2]), "=r"(r[3]) : "r"(addr));
}
__device__ __forceinline__ void ldm_x4t(uint32_t* r, uint32_t addr) {
    asm volatile("ldmatrix.sync.aligned.m8n8.x4.trans.shared.b16 {%0,%1,%2,%3}, [%4];"
                 : "=r"(r[0]), "=r"(r[1]), "=r"(r[2]), "=r"(r[3]) : "r"(addr));
}
__device__ __forceinline__ void mma_f16(float* d, const uint32_t* a, const uint32_t* b) {
    asm volatile(
        "mma.sync.aligned.m16n8k16.row.col.f32.f16.f16.f32 "
        "{%0,%1,%2,%3}, {%4,%5,%6,%7}, {%8,%9}, {%0,%1,%2,%3};"
        : "+f"(d[0]), "+f"(d[1]), "+f"(d[2]), "+f"(d[3])
        : "r"(a[0]), "r"(a[1]), "r"(a[2]), "r"(a[3]), "r"(b[0]), "r"(b[1]));
}
// L1-bypassing async copy (cg: caches at L2 only; legal for 16B)
__device__ __forceinline__ void cp16(uint32_t dst, const void* src) {
    asm volatile("cp.async.cg.shared.global [%0], [%1], 16;"
                 :: "r"(dst), "l"(src) : "memory");
}

// ---------------------------------------------------------------------------
// Weight convert: all 4 weights, fp32 [O,C] -> fp16
// ---------------------------------------------------------------------------
__global__ void wconv_kernel(const float* __restrict__ W0, const float* __restrict__ W1,
                             const float* __restrict__ W2, const float* __restrict__ W3,
                             __half* __restrict__ Wh)
{
    const float* Ws[4] = {W0, W1, W2, W3};
    const int i = blockIdx.x * 256 + threadIdx.x;
    Wh[blockIdx.y * CC * CC + i] = __float2half(Ws[blockIdx.y][i]);
}

// ---------------------------------------------------------------------------
// Transpose + convert both inputs: X[b][c][l] fp32 -> XT[b][l][c] fp16
// grid (L/32, C/32, 2*B): z < B -> input_, else context_
// ---------------------------------------------------------------------------
__global__ __launch_bounds__(256) void tconv_kernel(
    const float* __restrict__ X0, const float* __restrict__ X1,
    __half* __restrict__ T0, __half* __restrict__ T1)
{
    __shared__ float t[32][33];
    const int l0 = blockIdx.x * 32, c0 = blockIdx.y * 32;
    const int b = blockIdx.z & (BB - 1);
    const bool second = blockIdx.z >= BB;
    const float* X = second ? X1 : X0;
    __half* Th = second ? T1 : T0;
    const float* xp = X + ((size_t)b * CC + c0) * LL + l0;
#pragma unroll
    for (int i = 0; i < 4; i++) {
        const int c = threadIdx.y + i * 8;
        t[c][threadIdx.x] = xp[(size_t)c * LL + threadIdx.x];
    }
    __syncthreads();
    __half* th = Th + ((size_t)b * LL + l0) * CC + c0;
#pragma unroll
    for (int i = 0; i < 4; i++) {
        const int row = threadIdx.y + i * 8;
        th[(size_t)row * CC + threadIdx.x] = __float2half(t[threadIdx.x][row]);
    }
}

// ---------------------------------------------------------------------------
// mma.sync fp16 GEMM, cp.async 3-stage pipeline, templated output type.
// ---------------------------------------------------------------------------
#define PADK 40
#define NCHUNK (CC / 32)
#define OFF_B 10240
#define STAGE_B 20480
#define GEMM_DSM (3 * STAGE_B)

template <typename OutT>
__global__ void __launch_bounds__(256, 2) gemm_mma_kernel(
    const __half* __restrict__ A, const __half* __restrict__ B,
    const float* __restrict__ bias, const float* __restrict__ resid,
    OutT* __restrict__ Y)
{
    extern __shared__ char dsm[];
    const uint32_t sbase = smem_u32(dsm);

    const int tid = threadIdx.x, lane = tid & 31, wid = tid >> 5;
    const int wm = wid >> 2, wn = wid & 3;
    const int b = blockIdx.z;
    const int n0 = blockIdx.x * 128;
    const int m0 = blockIdx.y * 128;

    const __half* Ar = A + (size_t)m0 * CC;
    const __half* Br = B + ((size_t)b * LL + n0) * CC;

    const int ldRow = tid >> 2;
    const int ldGrp = tid & 3;

    auto issue = [&](int kc) {
        const uint32_t sb = sbase + (uint32_t)(kc % 3) * STAGE_B;
        const size_t gc = (size_t)kc * 32 + ldGrp * 8;
#pragma unroll
        for (int p = 0; p < 2; p++) {
            const int row = ldRow + p * 64;
            const uint32_t so = sb + (uint32_t)(row * 80 + ldGrp * 16);
            const size_t go = (size_t)row * CC + gc;
            cp16(so, Ar + go);
            cp16(so + OFF_B, Br + go);
        }
        asm volatile("cp.async.commit_group;" ::: "memory");
    };

    float acc[4][4][4];
#pragma unroll
    for (int i = 0; i < 4; i++)
#pragma unroll
        for (int j = 0; j < 4; j++)
#pragma unroll
            for (int x = 0; x < 4; x++) acc[i][j][x] = 0.f;

    const uint32_t aRow = (uint32_t)(wm * 64) + (lane & 7) + (lane & 8);
    const uint32_t aKh = (lane & 16) >> 1;
    const uint32_t aOffB = (aRow * PADK + aKh) * 2;
    const uint32_t bRow2 = (uint32_t)(wn * 32) + ((lane & 16) >> 1) + (lane & 7);
    const uint32_t bOff2 = (bRow2 * PADK + (lane & 8)) * 2;

    issue(0);
    issue(1);

    for (int kc = 0; kc < NCHUNK; kc++) {
        if (kc + 1 < NCHUNK) {
            asm volatile("cp.async.wait_group 1;" ::: "memory");
        } else {
            asm volatile("cp.async.wait_group 0;" ::: "memory");
        }
        __syncthreads();
        if (kc + 2 < NCHUNK) issue(kc + 2);

        const uint32_t stb = sbase + (uint32_t)(kc % 3) * STAGE_B;
#pragma unroll
        for (int ks = 0; ks < 2; ks++) {
            const uint32_t kb = ks * 32;
            uint32_t fb[4][2];
#pragma unroll
            for (int p = 0; p < 2; p++) {
                uint32_t t4[4];
                ldm_x4(t4, stb + OFF_B + bOff2 + p * (16 * PADK * 2) + kb);
                fb[2 * p][0] = t4[0]; fb[2 * p][1] = t4[1];
                fb[2 * p + 1][0] = t4[2]; fb[2 * p + 1][1] = t4[3];
            }
#pragma unroll
            for (int mt = 0; mt < 4; mt++) {
                uint32_t fa[4];
                ldm_x4(fa, stb + aOffB + mt * (16 * PADK * 2) + kb);
#pragma unroll
                for (int nt = 0; nt < 4; nt++)
                    mma_f16(acc[mt][nt], fa, fb[nt]);
            }
        }
    }

    const int mbase = m0 + wm * 64 + (lane >> 2);
    const int nbase = n0 + wn * 32 + (lane & 3) * 2;
#pragma unroll
    for (int mt = 0; mt < 4; mt++) {
        const int m = mbase + mt * 16;
        const float bv0 = bias[m], bv1 = bias[m + 8];
        OutT* y0 = Y + ((size_t)b * CC + m) * LL + n0;
        OutT* y1 = y0 + (size_t)8 * LL;
#pragma unroll
        for (int nt = 0; nt < 4; nt++) {
            const int n = (nbase - n0) + nt * 8;
            float v00 = acc[mt][nt][0] + bv0;
            float v01 = acc[mt][nt][1] + bv0;
            float v10 = acc[mt][nt][2] + bv1;
            float v11 = acc[mt][nt][3] + bv1;
            if constexpr (sizeof(OutT) == 4) {
                if (resid) {
                    const float* r0 = resid + ((size_t)b * CC + m) * LL + n0;
                    const float2 q0 = *(const float2*)(r0 + n);
                    const float2 q1 = *(const float2*)(r0 + (size_t)8 * LL + n);
                    v00 += q0.x; v01 += q0.y; v10 += q1.x; v11 += q1.y;
                }
                *(float2*)(y0 + n) = make_float2(v00, v01);
                *(float2*)(y1 + n) = make_float2(v10, v11);
            } else {
                *(__half2*)(y0 + n) = __floats2half2_rn(v00, v01);
                *(__half2*)(y1 + n) = __floats2half2_rn(v10, v11);
            }
        }
    }
}

// ---------------------------------------------------------------------------
// kstats: per-(b,c) row of fp16 K over L: (max, 1/sum_exp). 1 block/row.
// ---------------------------------------------------------------------------
__global__ __launch_bounds__(256) void kstats_kernel(
    const __half* __restrict__ Kh, float2* __restrict__ ST)
{
    const __half* p = Kh + (size_t)blockIdx.x * LL;
    const int tid = threadIdx.x;
    float v[32];
    float m = -FLT_MAX;
#pragma unroll
    for (int k = 0; k < 4; k++) {
        const uint4 raw = *(const uint4*)(p + ((size_t)tid + k * 256) * 8);
        const __half2* h = (const __half2*)&raw;
#pragma unroll
        for (int j = 0; j < 4; j++) {
            const float2 f = __half22float2(h[j]);
            v[k * 8 + j * 2 + 0] = f.x;
            v[k * 8 + j * 2 + 1] = f.y;
            m = fmaxf(m, fmaxf(f.x, f.y));
        }
    }
    __shared__ float red[256];
    red[tid] = m; __syncthreads();
    for (int s = 128; s > 0; s >>= 1) {
        if (tid < s) red[tid] = fmaxf(red[tid], red[tid + s]);
        __syncthreads();
    }
    m = red[0];
    __syncthreads();
    float sum = 0.f;
#pragma unroll
    for (int i = 0; i < 32; i++) sum += __expf(v[i] - m);
    red[tid] = sum; __syncthreads();
    for (int s = 128; s > 0; s >>= 1) {
        if (tid < s) red[tid] += red[tid + s];
        __syncthreads();
    }
    if (tid == 0) ST[blockIdx.x] = make_float2(m, 1.f / red[0]);
}

__global__ void zero_ctx_kernel(float* __restrict__ C)
{
    C[blockIdx.x * 256 + threadIdx.x] = 0.f;
}

// ---------------------------------------------------------------------------
// ctx (tensor core): ctx[dk,dv] += inv[dk] * sum_l exp(K[dk,l]-m[dk]) * V[dv,l]
// ---------------------------------------------------------------------------
#define PADL 72

__global__ __launch_bounds__(128, 4) void ctx_tc_kernel(
    const __half* __restrict__ Kk, const __half* __restrict__ Vv,
    const float2* __restrict__ ST, float* __restrict__ CTX)
{
    __shared__ __half sP[64 * PADL];
    __shared__ __half sV[64 * PADL];
    const int b = blockIdx.z, h = blockIdx.y;
    const int tid = threadIdx.x, lane = tid & 31, wid = tid >> 5;
    const int wm = wid >> 1, wn = wid & 1;
    const __half* kp = Kk + ((size_t)b * CC + h * DD) * LL;
    const __half* vp = Vv + ((size_t)b * CC + h * DD) * LL;
    const float2* stp = ST + b * CC + h * DD;

    float acc[2][4][4];
#pragma unroll
    for (int i = 0; i < 2; i++)
#pragma unroll
        for (int j = 0; j < 4; j++)
#pragma unroll
            for (int x = 0; x < 4; x++) acc[i][j][x] = 0.f;

    const uint32_t sPb = smem_u32(sP), sVb = smem_u32(sV);
    const uint32_t aOff =
        (((uint32_t)(wm * 32) + (lane & 7) + (lane & 8)) * PADL + ((lane & 16) >> 1)) * 2;
    const uint32_t bOff =
        (((uint32_t)(wn * 32) + ((lane & 16) >> 1) + (lane & 7)) * PADL + (lane & 8)) * 2;

    for (int t = 0; t < 8; t++) {
        const int lt = blockIdx.x * 512 + t * 64;
#pragma unroll
        for (int it = 0; it < 4; it++) {
            const int id = tid + it * 128;
            const int row = id >> 3, l8 = (id & 7) * 8;
            const uint4 kraw = *(const uint4*)(kp + (size_t)row * LL + lt + l8);
            const float2 st = stp[row];
            const __half2* kh = (const __half2*)&kraw;
            __half hk[8];
#pragma unroll
            for (int j = 0; j < 4; j++) {
                const float2 f = __half22float2(kh[j]);
                hk[2 * j + 0] = __float2half(__expf(f.x - st.x));
                hk[2 * j + 1] = __float2half(__expf(f.y - st.x));
            }
            *(uint4*)(sP + row * PADL + l8) = *(const uint4*)hk;
            *(uint4*)(sV + row * PADL + l8) =
                *(const uint4*)(vp + (size_t)row * LL + lt + l8);
        }
        __syncthreads();
#pragma unroll
        for (int ks = 0; ks < 4; ks++) {
            const uint32_t kb = ks * 32;
            uint32_t fb[4][2];
#pragma unroll
            for (int p = 0; p < 2; p++) {
                uint32_t t4[4];
                ldm_x4(t4, sVb + bOff + p * (16 * PADL * 2) + kb);
                fb[2 * p][0] = t4[0]; fb[2 * p][1] = t4[1];
                fb[2 * p + 1][0] = t4[2]; fb[2 * p + 1][1] = t4[3];
            }
#pragma unroll
            for (int mt = 0; mt < 2; mt++) {
                uint32_t fa[4];
                ldm_x4(fa, sPb + aOff + mt * (16 * PADL * 2) + kb);
#pragma unroll
                for (int nt = 0; nt < 4; nt++)
                    mma_f16(acc[mt][nt], fa, fb[nt]);
            }
        }
        __syncthreads();
    }

    float* cpx = CTX + (size_t)(b * HH + h) * DD * DD;
#pragma unroll
    for (int mt = 0; mt < 2; mt++) {
        const int dk0 = wm * 32 + mt * 16 + (lane >> 2);
        const float inv0 = stp[dk0].y, inv1 = stp[dk0 + 8].y;
#pragma unroll
        for (int nt = 0; nt < 4; nt++) {
            const int dv = wn * 32 + nt * 8 + (lane & 3) * 2;
            atomicAdd(&cpx[dk0 * DD + dv],           acc[mt][nt][0] * inv0);
            atomicAdd(&cpx[dk0 * DD + dv + 1],       acc[mt][nt][1] * inv0);
            atomicAdd(&cpx[(dk0 + 8) * DD + dv],     acc[mt][nt][2] * inv1);
            atomicAdd(&cpx[(dk0 + 8) * DD + dv + 1], acc[mt][nt][3] * inv1);
        }
    }
}

// ---------------------------------------------------------------------------
// att (tensor core) with FUSED per-l q-softmax stats:
//   stage raw Q tile [64 dk][256 l] -> compute per-l max/sum in smem ->
//   rewrite as unnormalized exp -> MMA -> scale by 1/sum in epilogue.
// Output written transposed to XT fp16 [b][l][h*64+dv] via smem stage.
// grid (LL/256, HH, BB), 256 threads (8 warps, 2m x 4n).
// ---------------------------------------------------------------------------
#define PADQ 264   // P row: 256 l + 8 pad halves
#define PADT 72    // tsT row: 64 dv + 8 pad halves

__global__ __launch_bounds__(256, 2) void att_tc_kernel(
    const __half* __restrict__ Q, const float* __restrict__ CTX,
    __half* __restrict__ Th)
{
    __shared__ __half sA[64 * PADL];        // ctx^T [dv][dk]
    __shared__ __half sP[256 * PADT];       // P [64][PADQ], reused as tsT[256][PADT]
    __shared__ float sInv[256];
    const int b = blockIdx.z, h = blockIdx.y;
    const int lBase = blockIdx.x * 256;
    const int tid = threadIdx.x, lane = tid & 31, wid = tid >> 5;
    const int wm = wid >> 2, wn = wid & 3;

    // stage ctx^T (fp32 -> fp16)
    const float* cpx = CTX + (size_t)(b * HH + h) * DD * DD;
#pragma unroll
    for (int it = 0; it < 16; it++) {
        const int id = tid + it * 256;
        const int dv = id & 63, dk = id >> 6;
        sA[dv * PADL + dk] = __float2half(cpx[dk * DD + dv]);
    }
    // stage RAW Q [dk][l] (coalesced vector copy)
    const __half* qp = Q + ((size_t)b * CC + h * DD) * LL + lBase;
#pragma unroll
    for (int it = 0; it < 8; it++) {
        const int id = tid + it * 256;
        const int dk = id >> 5, l8 = (id & 31) * 8;
        *(uint4*)(sP + dk * PADQ + l8) = *(const uint4*)(qp + (size_t)dk * LL + l8);
    }
    __syncthreads();

    // per-l softmax stats: thread tid owns column l=tid (conflict-free)
    {
        float m = -FLT_MAX;
#pragma unroll
        for (int dk = 0; dk < DD; dk++)
            m = fmaxf(m, __half2float(sP[dk * PADQ + tid]));
        float s = 0.f;
#pragma unroll
        for (int dk = 0; dk < DD; dk++) {
            const float e = __expf(__half2float(sP[dk * PADQ + tid]) - m);
            s += e;
            sP[dk * PADQ + tid] = __float2half(e);
        }
        sInv[tid] = 1.f / s;
    }
    __syncthreads();

    float acc[2][8][4];
#pragma unroll
    for (int i = 0; i < 2; i++)
#pragma unroll
        for (int j = 0; j < 8; j++)
#pragma unroll
            for (int x = 0; x < 4; x++) acc[i][j][x] = 0.f;

    const uint32_t sAb = smem_u32(sA), sPb = smem_u32(sP);
    const uint32_t aOff =
        (((uint32_t)(wm * 32) + (lane & 7) + (lane & 8)) * PADL + ((lane & 16) >> 1)) * 2;
    const uint32_t bOffT =
        (((uint32_t)(lane & 15)) * PADQ + (uint32_t)(wn * 64) + ((lane & 16) >> 1)) * 2;

#pragma unroll
    for (int ks = 0; ks < 4; ks++) {
        uint32_t fa[2][4];
#pragma unroll
        for (int mt = 0; mt < 2; mt++)
            ldm_x4(fa[mt], sAb + aOff + mt * (16 * PADL * 2) + ks * 32);
        uint32_t fb[8][2];
#pragma unroll
        for (int p = 0; p < 4; p++) {
            uint32_t t4[4];
            ldm_x4t(t4, sPb + bOffT + (uint32_t)(ks * 16 * PADQ * 2) + p * 32);
            fb[2 * p][0] = t4[0]; fb[2 * p][1] = t4[1];
            fb[2 * p + 1][0] = t4[2]; fb[2 * p + 1][1] = t4[3];
        }
#pragma unroll
        for (int mt = 0; mt < 2; mt++)
#pragma unroll
            for (int nt = 0; nt < 8; nt++)
                mma_f16(acc[mt][nt], fa[mt], fb[nt]);
    }
    __syncthreads();

    // epilogue: normalize by sInv[l], transpose to tsT[l][dv], coalesced writes
    __half* tsT = sP;
#pragma unroll
    for (int mt = 0; mt < 2; mt++) {
        const int m = wm * 32 + mt * 16 + (lane >> 2);
#pragma unroll
        for (int nt = 0; nt < 8; nt++) {
            const int n = wn * 64 + nt * 8 + (lane & 3) * 2;
            const float i0 = sInv[n], i1 = sInv[n + 1];
            tsT[n * PADT + m]           = __float2half(acc[mt][nt][0] * i0);
            tsT[(n + 1) * PADT + m]     = __float2half(acc[mt][nt][1] * i1);
            tsT[n * PADT + m + 8]       = __float2half(acc[mt][nt][2] * i0);
            tsT[(n + 1) * PADT + m + 8] = __float2half(acc[mt][nt][3] * i1);
        }
    }
    __syncthreads();
    __half* outp = Th + ((size_t)b * LL + lBase + tid) * CC + h * DD;
#pragma unroll
    for (int j = 0; j < 8; j++)
        *(uint4*)(outp + j * 8) = *(const uint4*)(tsT + tid * PADT + j * 8);
}

// ---------------------------------------------------------------------------
extern "C" void kernel_launch(void* const* d_in, const int* in_sizes, int n_in,
                              void* d_out, int out_size)
{
    const float* input_ = (const float*)d_in[0];
    const float* context_ = (const float*)d_in[1];
    const float* Wk = (const float*)d_in[2];
    const float* bk = (const float*)d_in[3];
    const float* Wq = (const float*)d_in[4];
    const float* bq = (const float*)d_in[5];
    const float* Wv = (const float*)d_in[6];
    const float* bv = (const float*)d_in[7];
    const float* Wr = (const float*)d_in[8];
    const float* br = (const float*)d_in[9];
    float* out = (float*)d_out;

    __half *Qp, *Kp, *Vp;
    float* Cp;
    float2* STp;
    cudaGetSymbolAddress((void**)&Qp, g_Q);
    cudaGetSymbolAddress((void**)&Kp, g_K);
    cudaGetSymbolAddress((void**)&Vp, g_V);
    cudaGetSymbolAddress((void**)&Cp, g_CTX);
    cudaGetSymbolAddress((void**)&STp, g_KSTAT);

    __half *Xin, *Xctx, *Xatt, *Wp;
    cudaGetSymbolAddress((void**)&Xin, g_X_in);
    cudaGetSymbolAddress((void**)&Xctx, g_X_ctx);
    cudaGetSymbolAddress((void**)&Xatt, g_X_att);
    cudaGetSymbolAddress((void**)&Wp, g_W);

    static bool attr_set = false;
    if (!attr_set) {
        cudaFuncSetAttribute(gemm_mma_kernel<__half>,
                             cudaFuncAttributeMaxDynamicSharedMemorySize, GEMM_DSM);
        cudaFuncSetAttribute(gemm_mma_kernel<float>,
                             cudaFuncAttributeMaxDynamicSharedMemorySize, GEMM_DSM);
        attr_set = true;
    }

    wconv_kernel<<<dim3(CC * CC / 256, 4), 256>>>(Wq, Wk, Wv, Wr, Wp);

    // both input transposes in one launch
    tconv_kernel<<<dim3(LL / 32, CC / 32, 2 * BB), dim3(32, 8)>>>(
        input_, context_, Xin, Xctx);

    const dim3 gG(LL / 128, CC / 128, BB);
    gemm_mma_kernel<__half><<<gG, 256, GEMM_DSM>>>(Wp + 0 * CC * CC, Xin, bq, nullptr, Qp);
    gemm_mma_kernel<__half><<<gG, 256, GEMM_DSM>>>(Wp + 1 * CC * CC, Xctx, bk, nullptr, Kp);
    gemm_mma_kernel<__half><<<gG, 256, GEMM_DSM>>>(Wp + 2 * CC * CC, Xctx, bv, nullptr, Vp);

    kstats_kernel<<<BB * CC, 256>>>(Kp, STp);
    zero_ctx_kernel<<<(BB * HH * DD * DD) / 256, 256>>>(Cp);
    ctx_tc_kernel<<<dim3(16, HH, BB), 128>>>(Kp, Vp, STp, Cp);
    att_tc_kernel<<<dim3(LL / 256, HH, BB), 256>>>(Qp, Cp, Xatt);

    gemm_mma_kernel<float><<<gG, 256, GEMM_DSM>>>(Wp + 3 * CC * CC, Xatt, br, input_, out);
}

// round 11
// speedup vs baseline: 1.4243x; 1.0427x over previous
#include <cuda_runtime.h>
#include <cuda_fp16.h>
#include <math.h>
#include <float.h>
#include <stdint.h>

#define BB 8
#define CC 512
#define LL 8192
#define HH 8
#define DD 64

// ---------------------------------------------------------------------------
// Scratch (static device globals: allocation-free per harness rules)
// ---------------------------------------------------------------------------
static __device__ __align__(256) __half g_PT[(size_t)BB * LL * CC];  // softmaxQ, [b][l][c]
static __device__ __align__(256) __half g_K[(size_t)BB * CC * LL];
static __device__ __align__(256) __half g_V[(size_t)BB * CC * LL];
static __device__ float g_CTX[BB * HH * DD * DD];
static __device__ float2 g_KSTAT[BB * CC];                 // per-(b,c): (max, 1/sum)
static __device__ __align__(256) __half g_M[(size_t)BB * CC * CC];   // folded Wr@ctx^T

static __device__ __align__(256) __half g_X_in[(size_t)BB * LL * CC];
static __device__ __align__(256) __half g_X_ctx[(size_t)BB * LL * CC];
static __device__ __align__(256) __half g_W[4][CC * CC];

// ---------------------------------------------------------------------------
__device__ __forceinline__ uint32_t smem_u32(const void* p) {
    uint32_t a;
    asm("{ .reg .u64 t; cvta.to.shared.u64 t, %1; cvt.u32.u64 %0, t; }"
        : "=r"(a) : "l"(p));
    return a;
}
__device__ __forceinline__ void ldm_x4(uint32_t* r, uint32_t addr) {
    asm volatile("ldmatrix.sync.aligned.m8n8.x4.shared.b16 {%0,%1,%2,%3}, [%4];"
                 : "=r"(r[0]), "=r"(r[1]), "=r"(r[2]), "=r"(r[3]) : "r"(addr));
}
__device__ __forceinline__ void mma_f16(float* d, const uint32_t* a, const uint32_t* b) {
    asm volatile(
        "mma.sync.aligned.m16n8k16.row.col.f32.f16.f16.f32 "
        "{%0,%1,%2,%3}, {%4,%5,%6,%7}, {%8,%9}, {%0,%1,%2,%3};"
        : "+f"(d[0]), "+f"(d[1]), "+f"(d[2]), "+f"(d[3])
        : "r"(a[0]), "r"(a[1]), "r"(a[2]), "r"(a[3]), "r"(b[0]), "r"(b[1]));
}
__device__ __forceinline__ void cp16(uint32_t dst, const void* src) {
    asm volatile("cp.async.cg.shared.global [%0], [%1], 16;"
                 :: "r"(dst), "l"(src) : "memory");
}

// ---------------------------------------------------------------------------
// Weight convert: all 4 weights, fp32 [O,C] -> fp16
// ---------------------------------------------------------------------------
__global__ void wconv_kernel(const float* __restrict__ W0, const float* __restrict__ W1,
                             const float* __restrict__ W2, const float* __restrict__ W3,
                             __half* __restrict__ Wh)
{
    const float* Ws[4] = {W0, W1, W2, W3};
    const int i = blockIdx.x * 256 + threadIdx.x;
    Wh[blockIdx.y * CC * CC + i] = __float2half(Ws[blockIdx.y][i]);
}

// ---------------------------------------------------------------------------
// Transpose + convert both inputs: X[b][c][l] fp32 -> XT[b][l][c] fp16
// ---------------------------------------------------------------------------
__global__ __launch_bounds__(256) void tconv_kernel(
    const float* __restrict__ X0, const float* __restrict__ X1,
    __half* __restrict__ T0, __half* __restrict__ T1)
{
    __shared__ float t[32][33];
    const int l0 = blockIdx.x * 32, c0 = blockIdx.y * 32;
    const int b = blockIdx.z & (BB - 1);
    const bool second = blockIdx.z >= BB;
    const float* X = second ? X1 : X0;
    __half* Th = second ? T1 : T0;
    const float* xp = X + ((size_t)b * CC + c0) * LL + l0;
#pragma unroll
    for (int i = 0; i < 4; i++) {
        const int c = threadIdx.y + i * 8;
        t[c][threadIdx.x] = xp[(size_t)c * LL + threadIdx.x];
    }
    __syncthreads();
    __half* th = Th + ((size_t)b * LL + l0) * CC + c0;
#pragma unroll
    for (int i = 0; i < 4; i++) {
        const int row = threadIdx.y + i * 8;
        th[(size_t)row * CC + threadIdx.x] = __float2half(t[threadIdx.x][row]);
    }
}

// ---------------------------------------------------------------------------
// Shared GEMM mainloop pieces
// ---------------------------------------------------------------------------
#define PADK 40
#define NCHUNK (CC / 32)
#define OFF_B 10240
#define STAGE_B 20480
#define GEMM_DSM (3 * STAGE_B)

// ---------------------------------------------------------------------------
// Standard GEMM: Y[b, m, n] = sum_c A[(b)][m][c]*B[b][n][c] + bias (+resid)
// aStride: per-batch stride of A (0 = shared weights).
// ---------------------------------------------------------------------------
template <typename OutT>
__global__ void __launch_bounds__(256, 2) gemm_mma_kernel(
    const __half* __restrict__ A, size_t aStride, const __half* __restrict__ B,
    const float* __restrict__ bias, const float* __restrict__ resid,
    OutT* __restrict__ Y)
{
    extern __shared__ char dsm[];
    const uint32_t sbase = smem_u32(dsm);

    const int tid = threadIdx.x, lane = tid & 31, wid = tid >> 5;
    const int wm = wid >> 2, wn = wid & 3;
    const int b = blockIdx.z;
    const int n0 = blockIdx.x * 128;
    const int m0 = blockIdx.y * 128;

    const __half* Ar = A + (size_t)b * aStride + (size_t)m0 * CC;
    const __half* Br = B + ((size_t)b * LL + n0) * CC;

    const int ldRow = tid >> 2;
    const int ldGrp = tid & 3;

    auto issue = [&](int kc) {
        const uint32_t sb = sbase + (uint32_t)(kc % 3) * STAGE_B;
        const size_t gc = (size_t)kc * 32 + ldGrp * 8;
#pragma unroll
        for (int p = 0; p < 2; p++) {
            const int row = ldRow + p * 64;
            const uint32_t so = sb + (uint32_t)(row * 80 + ldGrp * 16);
            const size_t go = (size_t)row * CC + gc;
            cp16(so, Ar + go);
            cp16(so + OFF_B, Br + go);
        }
        asm volatile("cp.async.commit_group;" ::: "memory");
    };

    float acc[4][4][4];
#pragma unroll
    for (int i = 0; i < 4; i++)
#pragma unroll
        for (int j = 0; j < 4; j++)
#pragma unroll
            for (int x = 0; x < 4; x++) acc[i][j][x] = 0.f;

    const uint32_t aRow = (uint32_t)(wm * 64) + (lane & 7) + (lane & 8);
    const uint32_t aKh = (lane & 16) >> 1;
    const uint32_t aOffB = (aRow * PADK + aKh) * 2;
    const uint32_t bRow2 = (uint32_t)(wn * 32) + ((lane & 16) >> 1) + (lane & 7);
    const uint32_t bOff2 = (bRow2 * PADK + (lane & 8)) * 2;

    issue(0);
    issue(1);

    for (int kc = 0; kc < NCHUNK; kc++) {
        if (kc + 1 < NCHUNK) {
            asm volatile("cp.async.wait_group 1;" ::: "memory");
        } else {
            asm volatile("cp.async.wait_group 0;" ::: "memory");
        }
        __syncthreads();
        if (kc + 2 < NCHUNK) issue(kc + 2);

        const uint32_t stb = sbase + (uint32_t)(kc % 3) * STAGE_B;
#pragma unroll
        for (int ks = 0; ks < 2; ks++) {
            const uint32_t kb = ks * 32;
            uint32_t fb[4][2];
#pragma unroll
            for (int p = 0; p < 2; p++) {
                uint32_t t4[4];
                ldm_x4(t4, stb + OFF_B + bOff2 + p * (16 * PADK * 2) + kb);
                fb[2 * p][0] = t4[0]; fb[2 * p][1] = t4[1];
                fb[2 * p + 1][0] = t4[2]; fb[2 * p + 1][1] = t4[3];
            }
#pragma unroll
            for (int mt = 0; mt < 4; mt++) {
                uint32_t fa[4];
                ldm_x4(fa, stb + aOffB + mt * (16 * PADK * 2) + kb);
#pragma unroll
                for (int nt = 0; nt < 4; nt++)
                    mma_f16(acc[mt][nt], fa, fb[nt]);
            }
        }
    }

    const int mbase = m0 + wm * 64 + (lane >> 2);
    const int nbase = n0 + wn * 32 + (lane & 3) * 2;
#pragma unroll
    for (int mt = 0; mt < 4; mt++) {
        const int m = mbase + mt * 16;
        const float bv0 = bias[m], bv1 = bias[m + 8];
        OutT* y0 = Y + ((size_t)b * CC + m) * LL + n0;
        OutT* y1 = y0 + (size_t)8 * LL;
#pragma unroll
        for (int nt = 0; nt < 4; nt++) {
            const int n = (nbase - n0) + nt * 8;
            float v00 = acc[mt][nt][0] + bv0;
            float v01 = acc[mt][nt][1] + bv0;
            float v10 = acc[mt][nt][2] + bv1;
            float v11 = acc[mt][nt][3] + bv1;
            if constexpr (sizeof(OutT) == 4) {
                if (resid) {
                    const float* r0 = resid + ((size_t)b * CC + m) * LL + n0;
                    const float2 q0 = *(const float2*)(r0 + n);
                    const float2 q1 = *(const float2*)(r0 + (size_t)8 * LL + n);
                    v00 += q0.x; v01 += q0.y; v10 += q1.x; v11 += q1.y;
                }
                *(float2*)(y0 + n) = make_float2(v00, v01);
                *(float2*)(y1 + n) = make_float2(v10, v11);
            } else {
                *(__half2*)(y0 + n) = __floats2half2_rn(v00, v01);
                *(__half2*)(y1 + n) = __floats2half2_rn(v10, v11);
            }
        }
    }
}

// ---------------------------------------------------------------------------
// Q-projection GEMM with FUSED softmax over head channels + transpose:
// Each warp's 64 m-rows = one full head. For each output column l, softmax
// over the 64 channels is an in-register reduction (4 mt x 2 rows) plus
// shfl.xor(4,8,16) across the 8 lanes sharing that column. Result written
// fp16 to PT[b][l][c] via smem transpose (reusing the pipeline smem).
// ---------------------------------------------------------------------------
#define PADP 136   // sT row: 128 c + 8 pad halves

__global__ void __launch_bounds__(256, 2) qgemm_kernel(
    const __half* __restrict__ A, const __half* __restrict__ B,
    const float* __restrict__ bias, __half* __restrict__ PT)
{
    extern __shared__ char dsm[];
    const uint32_t sbase = smem_u32(dsm);

    const int tid = threadIdx.x, lane = tid & 31, wid = tid >> 5;
    const int wm = wid >> 2, wn = wid & 3;
    const int b = blockIdx.z;
    const int n0 = blockIdx.x * 128;
    const int m0 = blockIdx.y * 128;

    const __half* Ar = A + (size_t)m0 * CC;
    const __half* Br = B + ((size_t)b * LL + n0) * CC;

    const int ldRow = tid >> 2;
    const int ldGrp = tid & 3;

    auto issue = [&](int kc) {
        const uint32_t sb = sbase + (uint32_t)(kc % 3) * STAGE_B;
        const size_t gc = (size_t)kc * 32 + ldGrp * 8;
#pragma unroll
        for (int p = 0; p < 2; p++) {
            const int row = ldRow + p * 64;
            const uint32_t so = sb + (uint32_t)(row * 80 + ldGrp * 16);
            const size_t go = (size_t)row * CC + gc;
            cp16(so, Ar + go);
            cp16(so + OFF_B, Br + go);
        }
        asm volatile("cp.async.commit_group;" ::: "memory");
    };

    float acc[4][4][4];
#pragma unroll
    for (int i = 0; i < 4; i++)
#pragma unroll
        for (int j = 0; j < 4; j++)
#pragma unroll
            for (int x = 0; x < 4; x++) acc[i][j][x] = 0.f;

    const uint32_t aRow = (uint32_t)(wm * 64) + (lane & 7) + (lane & 8);
    const uint32_t aKh = (lane & 16) >> 1;
    const uint32_t aOffB = (aRow * PADK + aKh) * 2;
    const uint32_t bRow2 = (uint32_t)(wn * 32) + ((lane & 16) >> 1) + (lane & 7);
    const uint32_t bOff2 = (bRow2 * PADK + (lane & 8)) * 2;

    issue(0);
    issue(1);

    for (int kc = 0; kc < NCHUNK; kc++) {
        if (kc + 1 < NCHUNK) {
            asm volatile("cp.async.wait_group 1;" ::: "memory");
        } else {
            asm volatile("cp.async.wait_group 0;" ::: "memory");
        }
        __syncthreads();
        if (kc + 2 < NCHUNK) issue(kc + 2);

        const uint32_t stb = sbase + (uint32_t)(kc % 3) * STAGE_B;
#pragma unroll
        for (int ks = 0; ks < 2; ks++) {
            const uint32_t kb = ks * 32;
            uint32_t fb[4][2];
#pragma unroll
            for (int p = 0; p < 2; p++) {
                uint32_t t4[4];
                ldm_x4(t4, stb + OFF_B + bOff2 + p * (16 * PADK * 2) + kb);
                fb[2 * p][0] = t4[0]; fb[2 * p][1] = t4[1];
                fb[2 * p + 1][0] = t4[2]; fb[2 * p + 1][1] = t4[3];
            }
#pragma unroll
            for (int mt = 0; mt < 4; mt++) {
                uint32_t fa[4];
                ldm_x4(fa, stb + aOffB + mt * (16 * PADK * 2) + kb);
#pragma unroll
                for (int nt = 0; nt < 4; nt++)
                    mma_f16(acc[mt][nt], fa, fb[nt]);
            }
        }
    }
    __syncthreads();   // all warps done with pipeline smem; safe to reuse

    // bias add (per m-row)
#pragma unroll
    for (int mt = 0; mt < 4; mt++) {
        const int m = m0 + wm * 64 + mt * 16 + (lane >> 2);
        const float bv0 = bias[m], bv1 = bias[m + 8];
#pragma unroll
        for (int nt = 0; nt < 4; nt++) {
            acc[mt][nt][0] += bv0; acc[mt][nt][1] += bv0;
            acc[mt][nt][2] += bv1; acc[mt][nt][3] += bv1;
        }
    }

    // per-column softmax over the warp's 64 rows (= one head) + smem transpose
    __half* sT = (__half*)dsm;                 // [128 l][PADP c]
    const int crow = wm * 64 + (lane >> 2);    // +mt*16, +8
#pragma unroll
    for (int nt = 0; nt < 4; nt++) {
        float m0c = -FLT_MAX, m1c = -FLT_MAX;
#pragma unroll
        for (int mt = 0; mt < 4; mt++) {
            m0c = fmaxf(m0c, fmaxf(acc[mt][nt][0], acc[mt][nt][2]));
            m1c = fmaxf(m1c, fmaxf(acc[mt][nt][1], acc[mt][nt][3]));
        }
#pragma unroll
        for (int off = 4; off <= 16; off <<= 1) {
            m0c = fmaxf(m0c, __shfl_xor_sync(0xffffffffu, m0c, off));
            m1c = fmaxf(m1c, __shfl_xor_sync(0xffffffffu, m1c, off));
        }
        float s0 = 0.f, s1 = 0.f;
#pragma unroll
        for (int mt = 0; mt < 4; mt++) {
            acc[mt][nt][0] = __expf(acc[mt][nt][0] - m0c); s0 += acc[mt][nt][0];
            acc[mt][nt][2] = __expf(acc[mt][nt][2] - m0c); s0 += acc[mt][nt][2];
            acc[mt][nt][1] = __expf(acc[mt][nt][1] - m1c); s1 += acc[mt][nt][1];
            acc[mt][nt][3] = __expf(acc[mt][nt][3] - m1c); s1 += acc[mt][nt][3];
        }
#pragma unroll
        for (int off = 4; off <= 16; off <<= 1) {
            s0 += __shfl_xor_sync(0xffffffffu, s0, off);
            s1 += __shfl_xor_sync(0xffffffffu, s1, off);
        }
        const float i0 = 1.f / s0, i1 = 1.f / s1;
        const int l0c = wn * 32 + nt * 8 + (lane & 3) * 2;
#pragma unroll
        for (int mt = 0; mt < 4; mt++) {
            const int c = crow + mt * 16;
            sT[l0c * PADP + c]           = __float2half(acc[mt][nt][0] * i0);
            sT[(l0c + 1) * PADP + c]     = __float2half(acc[mt][nt][1] * i1);
            sT[l0c * PADP + c + 8]       = __float2half(acc[mt][nt][2] * i0);
            sT[(l0c + 1) * PADP + c + 8] = __float2half(acc[mt][nt][3] * i1);
        }
    }
    __syncthreads();

    // coalesced write: PT[b][n0+l][m0 .. m0+127]
    const int cg = tid & 15;          // 16B group within the 128-ch slice
    const int lr = tid >> 4;          // 16 rows per pass
#pragma unroll
    for (int it = 0; it < 8; it++) {
        const int l = it * 16 + lr;
        *(uint4*)(PT + ((size_t)b * LL + n0 + l) * CC + m0 + cg * 8) =
            *(const uint4*)(sT + l * PADP + cg * 8);
    }
}

// ---------------------------------------------------------------------------
// kstats: per-(b,c) row of fp16 K over L: (max, 1/sum_exp). 1 block/row.
// ---------------------------------------------------------------------------
__global__ __launch_bounds__(256) void kstats_kernel(
    const __half* __restrict__ Kh, float2* __restrict__ ST)
{
    const __half* p = Kh + (size_t)blockIdx.x * LL;
    const int tid = threadIdx.x;
    float v[32];
    float m = -FLT_MAX;
#pragma unroll
    for (int k = 0; k < 4; k++) {
        const uint4 raw = *(const uint4*)(p + ((size_t)tid + k * 256) * 8);
        const __half2* h = (const __half2*)&raw;
#pragma unroll
        for (int j = 0; j < 4; j++) {
            const float2 f = __half22float2(h[j]);
            v[k * 8 + j * 2 + 0] = f.x;
            v[k * 8 + j * 2 + 1] = f.y;
            m = fmaxf(m, fmaxf(f.x, f.y));
        }
    }
    __shared__ float red[256];
    red[tid] = m; __syncthreads();
    for (int s = 128; s > 0; s >>= 1) {
        if (tid < s) red[tid] = fmaxf(red[tid], red[tid + s]);
        __syncthreads();
    }
    m = red[0];
    __syncthreads();
    float sum = 0.f;
#pragma unroll
    for (int i = 0; i < 32; i++) sum += __expf(v[i] - m);
    red[tid] = sum; __syncthreads();
    for (int s = 128; s > 0; s >>= 1) {
        if (tid < s) red[tid] += red[tid + s];
        __syncthreads();
    }
    if (tid == 0) ST[blockIdx.x] = make_float2(m, 1.f / red[0]);
}

__global__ void zero_ctx_kernel(float* __restrict__ C)
{
    C[blockIdx.x * 256 + threadIdx.x] = 0.f;
}

// ---------------------------------------------------------------------------
// ctx (tensor core): ctx[dk,dv] += inv[dk] * sum_l exp(K[dk,l]-m[dk]) * V[dv,l]
// ---------------------------------------------------------------------------
#define PADL 72

__global__ __launch_bounds__(128, 4) void ctx_tc_kernel(
    const __half* __restrict__ Kk, const __half* __restrict__ Vv,
    const float2* __restrict__ ST, float* __restrict__ CTX)
{
    __shared__ __half sP[64 * PADL];
    __shared__ __half sV[64 * PADL];
    const int b = blockIdx.z, h = blockIdx.y;
    const int tid = threadIdx.x, lane = tid & 31, wid = tid >> 5;
    const int wm = wid >> 1, wn = wid & 1;
    const __half* kp = Kk + ((size_t)b * CC + h * DD) * LL;
    const __half* vp = Vv + ((size_t)b * CC + h * DD) * LL;
    const float2* stp = ST + b * CC + h * DD;

    float acc[2][4][4];
#pragma unroll
    for (int i = 0; i < 2; i++)
#pragma unroll
        for (int j = 0; j < 4; j++)
#pragma unroll
            for (int x = 0; x < 4; x++) acc[i][j][x] = 0.f;

    const uint32_t sPb = smem_u32(sP), sVb = smem_u32(sV);
    const uint32_t aOff =
        (((uint32_t)(wm * 32) + (lane & 7) + (lane & 8)) * PADL + ((lane & 16) >> 1)) * 2;
    const uint32_t bOff =
        (((uint32_t)(wn * 32) + ((lane & 16) >> 1) + (lane & 7)) * PADL + (lane & 8)) * 2;

    for (int t = 0; t < 8; t++) {
        const int lt = blockIdx.x * 512 + t * 64;
#pragma unroll
        for (int it = 0; it < 4; it++) {
            const int id = tid + it * 128;
            const int row = id >> 3, l8 = (id & 7) * 8;
            const uint4 kraw = *(const uint4*)(kp + (size_t)row * LL + lt + l8);
            const float2 st = stp[row];
            const __half2* kh = (const __half2*)&kraw;
            __half hk[8];
#pragma unroll
            for (int j = 0; j < 4; j++) {
                const float2 f = __half22float2(kh[j]);
                hk[2 * j + 0] = __float2half(__expf(f.x - st.x));
                hk[2 * j + 1] = __float2half(__expf(f.y - st.x));
            }
            *(uint4*)(sP + row * PADL + l8) = *(const uint4*)hk;
            *(uint4*)(sV + row * PADL + l8) =
                *(const uint4*)(vp + (size_t)row * LL + lt + l8);
        }
        __syncthreads();
#pragma unroll
        for (int ks = 0; ks < 4; ks++) {
            const uint32_t kb = ks * 32;
            uint32_t fb[4][2];
#pragma unroll
            for (int p = 0; p < 2; p++) {
                uint32_t t4[4];
                ldm_x4(t4, sVb + bOff + p * (16 * PADL * 2) + kb);
                fb[2 * p][0] = t4[0]; fb[2 * p][1] = t4[1];
                fb[2 * p + 1][0] = t4[2]; fb[2 * p + 1][1] = t4[3];
            }
#pragma unroll
            for (int mt = 0; mt < 2; mt++) {
                uint32_t fa[4];
                ldm_x4(fa, sPb + aOff + mt * (16 * PADL * 2) + kb);
#pragma unroll
                for (int nt = 0; nt < 4; nt++)
                    mma_f16(acc[mt][nt], fa, fb[nt]);
            }
        }
        __syncthreads();
    }

    float* cpx = CTX + (size_t)(b * HH + h) * DD * DD;
#pragma unroll
    for (int mt = 0; mt < 2; mt++) {
        const int dk0 = wm * 32 + mt * 16 + (lane >> 2);
        const float inv0 = stp[dk0].y, inv1 = stp[dk0 + 8].y;
#pragma unroll
        for (int nt = 0; nt < 4; nt++) {
            const int dv = wn * 32 + nt * 8 + (lane & 3) * 2;
            atomicAdd(&cpx[dk0 * DD + dv],           acc[mt][nt][0] * inv0);
            atomicAdd(&cpx[dk0 * DD + dv + 1],       acc[mt][nt][1] * inv0);
            atomicAdd(&cpx[(dk0 + 8) * DD + dv],     acc[mt][nt][2] * inv1);
            atomicAdd(&cpx[(dk0 + 8) * DD + dv + 1], acc[mt][nt][3] * inv1);
        }
    }
}

// ---------------------------------------------------------------------------
// Fold Wr into ctx: M[b][c][h*64+dk] = sum_dv Wr[c][h*64+dv] * ctxN[b,h][dk][dv]
// grid (CC/64, HH, BB), 256 threads. thread = (c = tid&63, dk group = tid>>6).
// ---------------------------------------------------------------------------
__global__ __launch_bounds__(256) void mctx_kernel(
    const __half* __restrict__ Wr, const float* __restrict__ CTX,
    __half* __restrict__ M)
{
    __shared__ float sc[DD][DD + 1];     // [dk][dv]
    const int b = blockIdx.z, h = blockIdx.y, c0 = blockIdx.x * 64;
    const float* cp = CTX + (size_t)(b * HH + h) * DD * DD;
    for (int i = threadIdx.x; i < DD * DD; i += 256)
        sc[i >> 6][i & 63] = cp[i];
    __syncthreads();

    const int c = c0 + (threadIdx.x & 63);
    const int dk0 = (threadIdx.x >> 6) * 16;
    const __half* wp = Wr + (size_t)c * CC + h * DD;
    float w[DD];
#pragma unroll
    for (int dv = 0; dv < DD; dv += 8) {
        const uint4 raw = *(const uint4*)(wp + dv);
        const __half2* hh = (const __half2*)&raw;
#pragma unroll
        for (int j = 0; j < 4; j++) {
            const float2 f = __half22float2(hh[j]);
            w[dv + 2 * j] = f.x; w[dv + 2 * j + 1] = f.y;
        }
    }
    __half out[16];
#pragma unroll
    for (int kk = 0; kk < 16; kk++) {
        float s = 0.f;
#pragma unroll
        for (int dv = 0; dv < DD; dv++)
            s = fmaf(w[dv], sc[dk0 + kk][dv], s);
        out[kk] = __float2half(s);
    }
    __half* mp = M + ((size_t)b * CC + c) * CC + h * DD + dk0;
    *(uint4*)(mp)     = *(const uint4*)(out);
    *(uint4*)(mp + 8) = *(const uint4*)(out + 8);
}

// ---------------------------------------------------------------------------
extern "C" void kernel_launch(void* const* d_in, const int* in_sizes, int n_in,
                              void* d_out, int out_size)
{
    const float* input_ = (const float*)d_in[0];
    const float* context_ = (const float*)d_in[1];
    const float* Wk = (const float*)d_in[2];
    const float* bk = (const float*)d_in[3];
    const float* Wq = (const float*)d_in[4];
    const float* bq = (const float*)d_in[5];
    const float* Wv = (const float*)d_in[6];
    const float* bv = (const float*)d_in[7];
    const float* Wr = (const float*)d_in[8];
    const float* br = (const float*)d_in[9];
    float* out = (float*)d_out;

    __half *PTp, *Kp, *Vp, *Mp;
    float* Cp;
    float2* STp;
    cudaGetSymbolAddress((void**)&PTp, g_PT);
    cudaGetSymbolAddress((void**)&Kp, g_K);
    cudaGetSymbolAddress((void**)&Vp, g_V);
    cudaGetSymbolAddress((void**)&Mp, g_M);
    cudaGetSymbolAddress((void**)&Cp, g_CTX);
    cudaGetSymbolAddress((void**)&STp, g_KSTAT);

    __half *Xin, *Xctx, *Wp;
    cudaGetSymbolAddress((void**)&Xin, g_X_in);
    cudaGetSymbolAddress((void**)&Xctx, g_X_ctx);
    cudaGetSymbolAddress((void**)&Wp, g_W);

    static bool attr_set = false;
    if (!attr_set) {
        cudaFuncSetAttribute(gemm_mma_kernel<__half>,
                             cudaFuncAttributeMaxDynamicSharedMemorySize, GEMM_DSM);
        cudaFuncSetAttribute(gemm_mma_kernel<float>,
                             cudaFuncAttributeMaxDynamicSharedMemorySize, GEMM_DSM);
        cudaFuncSetAttribute(qgemm_kernel,
                             cudaFuncAttributeMaxDynamicSharedMemorySize, GEMM_DSM);
        attr_set = true;
    }

    wconv_kernel<<<dim3(CC * CC / 256, 4), 256>>>(Wq, Wk, Wv, Wr, Wp);
    tconv_kernel<<<dim3(LL / 32, CC / 32, 2 * BB), dim3(32, 8)>>>(
        input_, context_, Xin, Xctx);

    const dim3 gG(LL / 128, CC / 128, BB);
    // Q projection with fused softmax -> PT[b][l][c]
    qgemm_kernel<<<gG, 256, GEMM_DSM>>>(Wp + 0 * CC * CC, Xin, bq, PTp);
    gemm_mma_kernel<__half><<<gG, 256, GEMM_DSM>>>(Wp + 1 * CC * CC, 0, Xctx, bk, nullptr, Kp);
    gemm_mma_kernel<__half><<<gG, 256, GEMM_DSM>>>(Wp + 2 * CC * CC, 0, Xctx, bv, nullptr, Vp);

    kstats_kernel<<<BB * CC, 256>>>(Kp, STp);
    zero_ctx_kernel<<<(BB * HH * DD * DD) / 256, 256>>>(Cp);
    ctx_tc_kernel<<<dim3(16, HH, BB), 128>>>(Kp, Vp, STp, Cp);
    // fold Wr @ ctx^T -> per-batch M
    mctx_kernel<<<dim3(CC / 64, HH, BB), 256>>>(Wp + 3 * CC * CC, Cp, Mp);

    // out = M_b @ P + br + input_
    gemm_mma_kernel<float><<<gG, 256, GEMM_DSM>>>(Mp, (size_t)CC * CC, PTp, br, input_, out);
}